// round 6
// baseline (speedup 1.0000x reference)
#include <cuda_runtime.h>
#include <math.h>

#define Mr 32768
#define GDc 384
#define NFFT 16384
#define HALFN 8192
#define SCALE_U (1.0f / (16384.0f * 16384.0f))

// smem physical index swizzle: inject bits [4:5] into [0:1] and [2:3]
__device__ __forceinline__ int PH(int e) {
    int m = (e >> 4) & 3;
    return e ^ (m | (m << 2));
}
__device__ __forceinline__ float2 cmul(float2 a, float2 b) {
    return make_float2(a.x * b.x - a.y * b.y, a.x * b.y + a.y * b.x);
}
__device__ __forceinline__ float2 cadd(float2 a, float2 b) { return make_float2(a.x + b.x, a.y + b.y); }
__device__ __forceinline__ float2 csub(float2 a, float2 b) { return make_float2(a.x - b.x, a.y - b.y); }

// ---- packed f32x2 helpers (Blackwell FFMA2) ----
__device__ __forceinline__ unsigned long long pk2(float lo, float hi) {
    unsigned long long r;
    asm("mov.b64 %0, {%1, %2};" : "=l"(r) : "f"(lo), "f"(hi));
    return r;
}
__device__ __forceinline__ void upk2(float& lo, float& hi, unsigned long long v) {
    asm("mov.b64 {%0, %1}, %2;" : "=f"(lo), "=f"(hi) : "l"(v));
}
__device__ __forceinline__ void fma2(unsigned long long& d, unsigned long long a, unsigned long long b) {
    asm("fma.rn.f32x2 %0, %1, %2, %0;" : "+l"(d) : "l"(a), "l"(b));
}

// ---------------- scratch (device globals) ----------------
__device__ float  g_x   [(long long)Mr * GDc];          // emb @ W_proj [B,S,384]
__device__ float  g_zc  [(long long)Mr * GDc];          // conv out     [B,S,384]
__device__ float  g_t   [(long long)Mr * 128];          // rope(emb)
__device__ float  g_hmid[(long long)Mr * 128];          // gelu(LN(...))
__device__ float  g_hT  [(long long)4 * 2 * 128 * 8192];// h normalized [B,N,D,S]
__device__ float  g_vT  [(long long)4 * 128 * 8192];    // recurrence   [B,D,S]
__device__ float2 g_tw  [HALFN];                        // W_N^k

// ---------------- twiddles ----------------
__global__ void k_twiddle() {
    int k = blockIdx.x * 256 + threadIdx.x;
    double a = -2.0 * 3.14159265358979323846 * (double)k / (double)NFFT;
    g_tw[k] = make_float2((float)cos(a), (float)sin(a));
}

// ---------------- RoPE ----------------
__global__ void k_rope(const float* __restrict__ emb, const int* __restrict__ pos) {
    int idx = blockIdx.x * blockDim.x + threadIdx.x;
    if (idx >= Mr * 64) return;
    int j  = idx & 63;
    int bs = idx >> 6;
    float theta = exp2f(-(float)j * 0.20762050593046015f);
    float ang = (float)pos[bs] * theta;
    float sa, ca; sincosf(ang, &sa, &ca);
    float2 xv = *(const float2*)(emb + (size_t)bs * 128 + 2 * j);
    float2 o;
    o.x = xv.x * ca - xv.y * sa;
    o.y = xv.x * sa + xv.y * ca;
    *(float2*)(g_t + (size_t)bs * 128 + 2 * j) = o;
}

// ---------------- depthwise conv K=3 along S (float4 over channels) ----------------
__global__ __launch_bounds__(256)
void k_conv(const float* __restrict__ w, const float* __restrict__ bias) {
    __shared__ float ws[3 * 384];
    __shared__ float bs_[384];
    int t = threadIdx.x;
    for (int i = t; i < 384; i += 256) bs_[i] = bias[i];
    for (int i = t; i < 1152; i += 256) ws[i] = w[i];
    __syncthreads();

    int idx = blockIdx.x * 256 + t;
    if (idx >= Mr * 96) return;
    int cg = idx % 96;
    int bs = idx / 96;
    int s  = bs & 8191;
    int c  = cg * 4;
    const float* xp = g_x + (size_t)bs * GDc + c;
    float4 x1 = *(const float4*)xp;
    float4 acc;
    acc.x = bs_[c + 0] + x1.x * ws[(c + 0) * 3 + 1];
    acc.y = bs_[c + 1] + x1.y * ws[(c + 1) * 3 + 1];
    acc.z = bs_[c + 2] + x1.z * ws[(c + 2) * 3 + 1];
    acc.w = bs_[c + 3] + x1.w * ws[(c + 3) * 3 + 1];
    if (s > 0) {
        float4 x0 = *(const float4*)(xp - GDc);
        acc.x += x0.x * ws[(c + 0) * 3];
        acc.y += x0.y * ws[(c + 1) * 3];
        acc.z += x0.z * ws[(c + 2) * 3];
        acc.w += x0.w * ws[(c + 3) * 3];
    }
    if (s < 8191) {
        float4 x2 = *(const float4*)(xp + GDc);
        acc.x += x2.x * ws[(c + 0) * 3 + 2];
        acc.y += x2.y * ws[(c + 1) * 3 + 2];
        acc.z += x2.z * ws[(c + 2) * 3 + 2];
        acc.w += x2.w * ws[(c + 3) * 3 + 2];
    }
    *(float4*)(g_zc + (size_t)bs * GDc + c) = acc;
}

// ---------------- fused SGEMMs (packed f32x2 FMA + gmem prefetch) ----------------
// MODE 0: g_x = emb @ W_proj                       (NC=384)
// MODE 1: g_hmid = gelu(LN(g_t @ W1 + b1))         (NC=128)
// MODE 2: g_hT   = L1norm((g_hmid@W2+b2)*ffs), T   (NC=256)
// MODE 3: out    = v^T @ out_proj  (A k-major)     (NC=128)
template<int MODE>
__global__ __launch_bounds__(256)
void k_sgemm(const float* __restrict__ Aext, const float* __restrict__ W,
             const float* __restrict__ bias, const float* __restrict__ gain,
             const float* __restrict__ beta, float* __restrict__ Cext)
{
    constexpr int  NC   = (MODE == 0) ? 384 : (MODE == 2) ? 256 : 128;
    constexpr bool KMAJ = (MODE == 3);
    __shared__ float As[16 * 132];
    __shared__ float Bs[16 * 132];

    const int tid  = threadIdx.x;
    const int m0   = blockIdx.x * 128;
    const int n0   = blockIdx.y * 128;
    const int trow = tid >> 4;
    const int tcol = tid & 15;

    const float* A;
    if      (MODE == 0) A = Aext;
    else if (MODE == 1) A = g_t;
    else if (MODE == 2) A = g_hmid;
    else                A = g_vT;

    const float* Ak = nullptr;
    if (KMAJ) Ak = A + (size_t)(m0 >> 13) * (128 * 8192) + (m0 & 8191);

    float4 aR[2], bR[2];
    const int arr = tid >> 2, ac4 = tid & 3;
    const int kk8 = tid >> 5, c32 = tid & 31;

    auto fetch = [&](int kt) {
        if (KMAJ) {
#pragma unroll
            for (int r2 = 0; r2 < 2; r2++)
                aR[r2] = *(const float4*)(Ak + (size_t)(kt + kk8 + r2 * 8) * 8192 + (c32 << 2));
        } else {
#pragma unroll
            for (int r2 = 0; r2 < 2; r2++)
                aR[r2] = *(const float4*)(A + (size_t)(m0 + arr + (r2 << 6)) * 128 + kt + (ac4 << 2));
        }
#pragma unroll
        for (int r2 = 0; r2 < 2; r2++)
            bR[r2] = *(const float4*)(W + (size_t)(kt + kk8 + r2 * 8) * NC + n0 + (c32 << 2));
    };
    auto stage = [&]() {
        if (KMAJ) {
#pragma unroll
            for (int r2 = 0; r2 < 2; r2++)
                *(float4*)(As + (kk8 + r2 * 8) * 132 + (c32 << 2)) = aR[r2];
        } else {
#pragma unroll
            for (int r2 = 0; r2 < 2; r2++) {
                int row = arr + (r2 << 6);
                As[(ac4 * 4 + 0) * 132 + row] = aR[r2].x;
                As[(ac4 * 4 + 1) * 132 + row] = aR[r2].y;
                As[(ac4 * 4 + 2) * 132 + row] = aR[r2].z;
                As[(ac4 * 4 + 3) * 132 + row] = aR[r2].w;
            }
        }
#pragma unroll
        for (int r2 = 0; r2 < 2; r2++)
            *(float4*)(Bs + (kk8 + r2 * 8) * 132 + (c32 << 2)) = bR[r2];
    };

    unsigned long long acc2[8][4];
#pragma unroll
    for (int i = 0; i < 8; i++)
#pragma unroll
        for (int j = 0; j < 4; j++) acc2[i][j] = 0ull;

    fetch(0);
#pragma unroll 1
    for (int t8 = 0; t8 < 8; t8++) {
        stage();
        __syncthreads();
        if (t8 < 7) fetch((t8 + 1) * 16);
#pragma unroll
        for (int kk = 0; kk < 16; kk++) {
            float4 a0 = *(const float4*)(As + kk * 132 + (trow << 2));
            float4 a1 = *(const float4*)(As + kk * 132 + (trow << 2) + 64);
            float4 b0 = *(const float4*)(Bs + kk * 132 + (tcol << 2));
            float4 b1 = *(const float4*)(Bs + kk * 132 + (tcol << 2) + 64);
            unsigned long long bp[4] = { pk2(b0.x, b0.y), pk2(b0.z, b0.w),
                                         pk2(b1.x, b1.y), pk2(b1.z, b1.w) };
            float av[8] = {a0.x, a0.y, a0.z, a0.w, a1.x, a1.y, a1.z, a1.w};
#pragma unroll
            for (int i = 0; i < 8; i++) {
                unsigned long long ap = pk2(av[i], av[i]);
#pragma unroll
                for (int j = 0; j < 4; j++) fma2(acc2[i][j], ap, bp[j]);
            }
        }
        __syncthreads();
    }

    float acc[8][8];
#pragma unroll
    for (int i = 0; i < 8; i++)
#pragma unroll
        for (int j = 0; j < 4; j++) upk2(acc[i][2 * j], acc[i][2 * j + 1], acc2[i][j]);

    int colL[8];
#pragma unroll
    for (int j = 0; j < 8; j++) colL[j] = (tcol << 2) + (j < 4 ? j : 60 + j);

    if (MODE == 0 || MODE == 3) {
        float* C = (MODE == 0) ? g_x : Cext;
#pragma unroll
        for (int i = 0; i < 8; i++) {
            int row = (trow << 2) + (i < 4 ? i : 60 + i);
            float* cp = C + (size_t)(m0 + row) * NC + n0 + (tcol << 2);
            *(float4*)cp        = make_float4(acc[i][0], acc[i][1], acc[i][2], acc[i][3]);
            *(float4*)(cp + 64) = make_float4(acc[i][4], acc[i][5], acc[i][6], acc[i][7]);
        }
    } else if (MODE == 1) {
        float bj[8], gj[8], tj[8];
#pragma unroll
        for (int j = 0; j < 8; j++) { bj[j] = bias[colL[j]]; gj[j] = gain[colL[j]]; tj[j] = beta[colL[j]]; }
#pragma unroll
        for (int i = 0; i < 8; i++) {
            float s = 0.f, s2 = 0.f;
#pragma unroll
            for (int j = 0; j < 8; j++) {
                float x = acc[i][j] + bj[j];
                acc[i][j] = x; s += x; s2 += x * x;
            }
#pragma unroll
            for (int off = 1; off < 16; off <<= 1) {
                s  += __shfl_xor_sync(0xffffffffu, s,  off, 16);
                s2 += __shfl_xor_sync(0xffffffffu, s2, off, 16);
            }
            float mu  = s * (1.f / 128.f);
            float var = s2 * (1.f / 128.f) - mu * mu;
            float rs  = rsqrtf(var + 1e-5f);
            float o[8];
#pragma unroll
            for (int j = 0; j < 8; j++) {
                float xn = (acc[i][j] - mu) * rs * gj[j] + tj[j];
                o[j] = 0.5f * xn * (1.f + erff(xn * 0.70710678118654752f));
            }
            int row = (trow << 2) + (i < 4 ? i : 60 + i);
            float* cp = g_hmid + (size_t)(m0 + row) * 128 + (tcol << 2);
            *(float4*)cp        = make_float4(o[0], o[1], o[2], o[3]);
            *(float4*)(cp + 64) = make_float4(o[4], o[5], o[6], o[7]);
        }
    } else { // MODE 2
        float bj[8], gj[8];
#pragma unroll
        for (int j = 0; j < 8; j++) { bj[j] = bias[n0 + colL[j]]; gj[j] = gain[n0 + colL[j]]; }
        float rsc[8];
#pragma unroll
        for (int i = 0; i < 8; i++) {
            float s = 0.f;
#pragma unroll
            for (int j = 0; j < 8; j++) {
                float x = (acc[i][j] + bj[j]) * gj[j];
                acc[i][j] = x; s += fabsf(x);
            }
#pragma unroll
            for (int off = 1; off < 16; off <<= 1)
                s += __shfl_xor_sync(0xffffffffu, s, off, 16);
            rsc[i] = 1.f / (s + 1e-8f);
        }
        float* dst = g_hT + (size_t)((m0 >> 13) * 2 + (n0 >> 7)) * 128 * 8192;
        int s0 = (m0 & 8191) + (trow << 2);
#pragma unroll
        for (int j = 0; j < 8; j++) {
            float* dp = dst + (size_t)colL[j] * 8192 + s0;
            *(float4*)dp = make_float4(acc[0][j] * rsc[0], acc[1][j] * rsc[1],
                                       acc[2][j] * rsc[2], acc[3][j] * rsc[3]);
            *(float4*)(dp + 64) = make_float4(acc[4][j] * rsc[4], acc[5][j] * rsc[5],
                                              acc[6][j] * rsc[6], acc[7][j] * rsc[7]);
        }
    }
}

// ---------------- FFT recurrence: 1 CTA per (b,d), radix-4 passes ----------------
__global__ __launch_bounds__(1024)
void k_fftrec(const float* __restrict__ Bp) {
    extern __shared__ float2 sh[];
    int b = blockIdx.x >> 7, d = blockIdx.x & 127;
    int tid = threadIdx.x;
    const float* z = g_zc + (size_t)b * (8192 * 384) + (size_t)d * 24576;

    float v[8];
#pragma unroll
    for (int k = 0; k < 8; k++) v[k] = z[16384 + tid + k * 1024];

    for (int it = 0; it < 2; it++) {
        const float* h = g_hT + (size_t)((b * 2 + it) * 128 + d) * 8192;

#pragma unroll
        for (int jj = 0; jj < 4; jj++) {
            int j = tid + jj * 1024;
            float2 x0 = make_float2(v[jj],     h[j]);
            float2 x1 = make_float2(v[jj + 4], h[j + 4096]);
            float2 W1 = g_tw[j];
            float2 W2 = make_float2(W1.y, -W1.x);
            float2 W3 = cmul(W1, W1);
            float2 t02m = cmul(x0, W1);
            float2 t13m = cmul(x1, W2);
            sh[PH(j)]         = cadd(x0, x1);
            sh[PH(j + 4096)]  = cmul(csub(x0, x1), W3);
            sh[PH(j + 8192)]  = cadd(t02m, t13m);
            sh[PH(j + 12288)] = cmul(csub(t02m, t13m), W3);
        }
        __syncthreads();

#pragma unroll
        for (int lg = 11; lg >= 1; lg -= 2) {
            int half = 1 << (lg - 1);
#pragma unroll
            for (int jj = 0; jj < 4; jj++) {
                int j   = tid + jj * 1024;
                int off = j & (half - 1);
                int i   = ((j >> (lg - 1)) << (lg + 1)) + off;
                float2 x0 = sh[PH(i)];
                float2 x1 = sh[PH(i + half)];
                float2 x2 = sh[PH(i + 2 * half)];
                float2 x3 = sh[PH(i + 3 * half)];
                float2 W1 = g_tw[off << (13 - lg)];
                float2 W2 = make_float2(W1.y, -W1.x);
                float2 W3 = cmul(W1, W1);
                float2 t02p = cadd(x0, x2);
                float2 t02m = cmul(csub(x0, x2), W1);
                float2 t13p = cadd(x1, x3);
                float2 t13m = cmul(csub(x1, x3), W2);
                sh[PH(i)]            = cadd(t02p, t13p);
                sh[PH(i + half)]     = cmul(csub(t02p, t13p), W3);
                sh[PH(i + 2 * half)] = cadd(t02m, t13m);
                sh[PH(i + 3 * half)] = cmul(csub(t02m, t13m), W3);
            }
            __syncthreads();
        }

        float2 ur[16];
#pragma unroll
        for (int k = 0; k < 16; k++) {
            int p  = tid + k * 1024;
            int kk = __brev(p) >> 18;
            int k2 = (16384 - kk) & 16383;
            int p2 = __brev(k2) >> 18;
            float2 P = sh[PH(p)], Q = sh[PH(p2)];
            float vx = 0.5f * (P.x + Q.x), vy = 0.5f * (P.y - Q.y);
            float hx = 0.5f * (P.y + Q.y), hy = 0.5f * (Q.x - P.x);
            ur[k] = make_float2(vx * hx - vy * hy, vx * hy + vy * hx);
        }
        __syncthreads();
#pragma unroll
        for (int k = 0; k < 16; k++) sh[PH(tid + k * 1024)] = ur[k];
        __syncthreads();

#pragma unroll
        for (int lg = 0; lg <= 10; lg += 2) {
            int len = 1 << lg;
#pragma unroll
            for (int jj = 0; jj < 4; jj++) {
                int j   = tid + jj * 1024;
                int off = j & (len - 1);
                int i   = ((j >> lg) << (lg + 2)) + off;
                float2 x0 = sh[PH(i)];
                float2 x1 = sh[PH(i + len)];
                float2 x2 = sh[PH(i + 2 * len)];
                float2 x3 = sh[PH(i + 3 * len)];
                float2 w   = g_tw[off << (12 - lg)];
                float2 cw2 = make_float2(w.x, -w.y);
                float2 cw1 = cmul(cw2, cw2);
                float2 cw3 = make_float2(-cw2.y, cw2.x);
                float2 b1 = cmul(x1, cw1);
                float2 b3 = cmul(x3, cw1);
                float2 u0 = cadd(x0, b1), u1 = csub(x0, b1);
                float2 u2 = cadd(x2, b3), u3 = csub(x2, b3);
                float2 c2 = cmul(u2, cw2);
                float2 c3 = cmul(u3, cw3);
                sh[PH(i)]           = cadd(u0, c2);
                sh[PH(i + 2 * len)] = csub(u0, c2);
                sh[PH(i + len)]     = cadd(u1, c3);
                sh[PH(i + 3 * len)] = csub(u1, c3);
            }
            __syncthreads();
        }

        const float* zn = z + it * 8192;
        float Bn = Bp[it * 128 + d];
#pragma unroll
        for (int jj = 0; jj < 4; jj++) {
            int j = tid + jj * 1024;
            float2 x0 = sh[PH(j)];
            float2 x1 = sh[PH(j + 4096)];
            float2 x2 = sh[PH(j + 8192)];
            float2 x3 = sh[PH(j + 12288)];
            float2 w   = g_tw[j];
            float2 cw2 = make_float2(w.x, -w.y);
            float2 cw1 = cmul(cw2, cw2);
            float2 cw3 = make_float2(-cw2.y, cw2.x);
            float2 b1 = cmul(x1, cw1);
            float2 b3 = cmul(x3, cw1);
            float2 u0 = cadd(x0, b1), u1 = csub(x0, b1);
            float2 u2 = cadd(x2, b3), u3 = csub(x2, b3);
            float y0x = u0.x + (u2.x * cw2.x - u2.y * cw2.y);
            float y1x = u1.x + (u3.x * cw3.x - u3.y * cw3.y);
            v[jj]     = zn[j]        * (y0x * SCALE_U + Bn * v[jj]);
            v[jj + 4] = zn[j + 4096] * (y1x * SCALE_U + Bn * v[jj + 4]);
        }
        __syncthreads();
    }
    float* vo = g_vT + (size_t)(b * 128 + d) * 8192;
#pragma unroll
    for (int k = 0; k < 8; k++) vo[tid + k * 1024] = v[k];
}

extern "C" void kernel_launch(void* const* d_in, const int* in_sizes, int n_in,
                              void* d_out, int out_size) {
    const float* emb = (const float*)d_in[0];
    const float* Wp  = (const float*)d_in[1];
    const float* cw  = (const float*)d_in[2];
    const float* cb  = (const float*)d_in[3];
    const float* W1  = (const float*)d_in[4];
    const float* b1  = (const float*)d_in[5];
    const float* lng = (const float*)d_in[6];
    const float* lnb = (const float*)d_in[7];
    const float* W2  = (const float*)d_in[8];
    const float* b2  = (const float*)d_in[9];
    const float* ffs = (const float*)d_in[10];
    const float* op  = (const float*)d_in[11];
    const float* Bp  = (const float*)d_in[12];
    const int*   pos = (const int*)d_in[13];
    float* out = (float*)d_out;

    cudaFuncSetAttribute(k_fftrec, cudaFuncAttributeMaxDynamicSharedMemorySize, 131072);

    k_twiddle<<<32, 256>>>();
    k_sgemm<0><<<dim3(256, 3), 256>>>(emb, Wp, nullptr, nullptr, nullptr, nullptr);
    k_conv<<<12288, 256>>>(cw, cb);
    k_rope<<<8192, 256>>>(emb, pos);
    k_sgemm<1><<<dim3(256, 1), 256>>>(nullptr, W1, b1, lng, lnb, nullptr);
    k_sgemm<2><<<dim3(256, 2), 256>>>(nullptr, W2, b2, ffs, nullptr, nullptr);
    k_fftrec<<<512, 1024, 131072>>>(Bp);
    k_sgemm<3><<<dim3(256, 1), 256>>>(nullptr, op, nullptr, nullptr, nullptr, out);
}

// round 7
// speedup vs baseline: 1.1117x; 1.1117x over previous
#include <cuda_runtime.h>
#include <math.h>

#define Mr 32768
#define GDc 384
#define NFFT 16384
#define HALFN 8192
#define SCALE_U (1.0f / (16384.0f * 16384.0f))

// padded smem index: conflict-free for strides {1,4,16,64,256,1024,4096}
__device__ __forceinline__ int PD(int e) { return e + (e >> 4) + (e >> 8); }

__device__ __forceinline__ float2 cmul(float2 a, float2 b) {
    return make_float2(a.x * b.x - a.y * b.y, a.x * b.y + a.y * b.x);
}
__device__ __forceinline__ float2 cadd(float2 a, float2 b) { return make_float2(a.x + b.x, a.y + b.y); }
__device__ __forceinline__ float2 csub(float2 a, float2 b) { return make_float2(a.x - b.x, a.y - b.y); }

// forward DIF radix-4 butterfly (in-place on registers)
__device__ __forceinline__ void fwd4(float2& x0, float2& x1, float2& x2, float2& x3, float2 W1) {
    float2 W2 = make_float2(W1.y, -W1.x);
    float2 W3 = cmul(W1, W1);
    float2 t02p = cadd(x0, x2), t02m = cmul(csub(x0, x2), W1);
    float2 t13p = cadd(x1, x3), t13m = cmul(csub(x1, x3), W2);
    x0 = cadd(t02p, t13p);
    x1 = cmul(csub(t02p, t13p), W3);
    x2 = cadd(t02m, t13m);
    x3 = cmul(csub(t02m, t13m), W3);
}
// inverse DIT radix-4 butterfly (in-place, conj twiddles)
__device__ __forceinline__ void inv4(float2& x0, float2& x1, float2& x2, float2& x3, float2 w) {
    float2 cw2 = make_float2(w.x, -w.y);
    float2 cw1 = cmul(cw2, cw2);
    float2 cw3 = make_float2(-cw2.y, cw2.x);
    float2 b1 = cmul(x1, cw1), b3 = cmul(x3, cw1);
    float2 u0 = cadd(x0, b1), u1 = csub(x0, b1);
    float2 u2 = cadd(x2, b3), u3 = csub(x2, b3);
    float2 c2 = cmul(u2, cw2), c3 = cmul(u3, cw3);
    x0 = cadd(u0, c2); x2 = csub(u0, c2);
    x1 = cadd(u1, c3); x3 = csub(u1, c3);
}

// ---- packed f32x2 helpers (Blackwell FFMA2) ----
__device__ __forceinline__ unsigned long long pk2(float lo, float hi) {
    unsigned long long r;
    asm("mov.b64 %0, {%1, %2};" : "=l"(r) : "f"(lo), "f"(hi));
    return r;
}
__device__ __forceinline__ void upk2(float& lo, float& hi, unsigned long long v) {
    asm("mov.b64 {%0, %1}, %2;" : "=f"(lo), "=f"(hi) : "l"(v));
}
__device__ __forceinline__ void fma2(unsigned long long& d, unsigned long long a, unsigned long long b) {
    asm("fma.rn.f32x2 %0, %1, %2, %0;" : "+l"(d) : "l"(a), "l"(b));
}

// ---------------- scratch (device globals) ----------------
__device__ float  g_x   [(long long)Mr * GDc];
__device__ float  g_zc  [(long long)Mr * GDc];
__device__ float  g_t   [(long long)Mr * 128];
__device__ float  g_hmid[(long long)Mr * 128];
__device__ float  g_hT  [(long long)4 * 2 * 128 * 8192];
__device__ float  g_vT  [(long long)4 * 128 * 8192];
__device__ float2 g_tw  [HALFN];

// ---------------- twiddles ----------------
__global__ void k_twiddle() {
    int k = blockIdx.x * 256 + threadIdx.x;
    double a = -2.0 * 3.14159265358979323846 * (double)k / (double)NFFT;
    g_tw[k] = make_float2((float)cos(a), (float)sin(a));
}

// ---------------- RoPE ----------------
__global__ void k_rope(const float* __restrict__ emb, const int* __restrict__ pos) {
    int idx = blockIdx.x * blockDim.x + threadIdx.x;
    if (idx >= Mr * 64) return;
    int j  = idx & 63;
    int bs = idx >> 6;
    float theta = exp2f(-(float)j * 0.20762050593046015f);
    float ang = (float)pos[bs] * theta;
    float sa, ca; sincosf(ang, &sa, &ca);
    float2 xv = *(const float2*)(emb + (size_t)bs * 128 + 2 * j);
    float2 o;
    o.x = xv.x * ca - xv.y * sa;
    o.y = xv.x * sa + xv.y * ca;
    *(float2*)(g_t + (size_t)bs * 128 + 2 * j) = o;
}

// ---------------- depthwise conv K=3 along S ----------------
__global__ __launch_bounds__(256)
void k_conv(const float* __restrict__ w, const float* __restrict__ bias) {
    __shared__ float ws[3 * 384];
    __shared__ float bs_[384];
    int t = threadIdx.x;
    for (int i = t; i < 384; i += 256) bs_[i] = bias[i];
    for (int i = t; i < 1152; i += 256) ws[i] = w[i];
    __syncthreads();

    int idx = blockIdx.x * 256 + t;
    if (idx >= Mr * 96) return;
    int cg = idx % 96;
    int bs = idx / 96;
    int s  = bs & 8191;
    int c  = cg * 4;
    const float* xp = g_x + (size_t)bs * GDc + c;
    float4 x1 = *(const float4*)xp;
    float4 acc;
    acc.x = bs_[c + 0] + x1.x * ws[(c + 0) * 3 + 1];
    acc.y = bs_[c + 1] + x1.y * ws[(c + 1) * 3 + 1];
    acc.z = bs_[c + 2] + x1.z * ws[(c + 2) * 3 + 1];
    acc.w = bs_[c + 3] + x1.w * ws[(c + 3) * 3 + 1];
    if (s > 0) {
        float4 x0 = *(const float4*)(xp - GDc);
        acc.x += x0.x * ws[(c + 0) * 3];
        acc.y += x0.y * ws[(c + 1) * 3];
        acc.z += x0.z * ws[(c + 2) * 3];
        acc.w += x0.w * ws[(c + 3) * 3];
    }
    if (s < 8191) {
        float4 x2 = *(const float4*)(xp + GDc);
        acc.x += x2.x * ws[(c + 0) * 3 + 2];
        acc.y += x2.y * ws[(c + 1) * 3 + 2];
        acc.z += x2.z * ws[(c + 2) * 3 + 2];
        acc.w += x2.w * ws[(c + 3) * 3 + 2];
    }
    *(float4*)(g_zc + (size_t)bs * GDc + c) = acc;
}

// ---------------- fused SGEMMs (FFMA2 + prefetch) ----------------
template<int MODE>
__global__ __launch_bounds__(256)
void k_sgemm(const float* __restrict__ Aext, const float* __restrict__ W,
             const float* __restrict__ bias, const float* __restrict__ gain,
             const float* __restrict__ beta, float* __restrict__ Cext)
{
    constexpr int  NC   = (MODE == 0) ? 384 : (MODE == 2) ? 256 : 128;
    constexpr bool KMAJ = (MODE == 3);
    __shared__ float As[16 * 132];
    __shared__ float Bs[16 * 132];

    const int tid  = threadIdx.x;
    const int m0   = blockIdx.x * 128;
    const int n0   = blockIdx.y * 128;
    const int trow = tid >> 4;
    const int tcol = tid & 15;

    const float* A;
    if      (MODE == 0) A = Aext;
    else if (MODE == 1) A = g_t;
    else if (MODE == 2) A = g_hmid;
    else                A = g_vT;

    const float* Ak = nullptr;
    if (KMAJ) Ak = A + (size_t)(m0 >> 13) * (128 * 8192) + (m0 & 8191);

    float4 aR[2], bR[2];
    const int arr = tid >> 2, ac4 = tid & 3;
    const int kk8 = tid >> 5, c32 = tid & 31;

    auto fetch = [&](int kt) {
        if (KMAJ) {
#pragma unroll
            for (int r2 = 0; r2 < 2; r2++)
                aR[r2] = *(const float4*)(Ak + (size_t)(kt + kk8 + r2 * 8) * 8192 + (c32 << 2));
        } else {
#pragma unroll
            for (int r2 = 0; r2 < 2; r2++)
                aR[r2] = *(const float4*)(A + (size_t)(m0 + arr + (r2 << 6)) * 128 + kt + (ac4 << 2));
        }
#pragma unroll
        for (int r2 = 0; r2 < 2; r2++)
            bR[r2] = *(const float4*)(W + (size_t)(kt + kk8 + r2 * 8) * NC + n0 + (c32 << 2));
    };
    auto stage = [&]() {
        if (KMAJ) {
#pragma unroll
            for (int r2 = 0; r2 < 2; r2++)
                *(float4*)(As + (kk8 + r2 * 8) * 132 + (c32 << 2)) = aR[r2];
        } else {
#pragma unroll
            for (int r2 = 0; r2 < 2; r2++) {
                int row = arr + (r2 << 6);
                As[(ac4 * 4 + 0) * 132 + row] = aR[r2].x;
                As[(ac4 * 4 + 1) * 132 + row] = aR[r2].y;
                As[(ac4 * 4 + 2) * 132 + row] = aR[r2].z;
                As[(ac4 * 4 + 3) * 132 + row] = aR[r2].w;
            }
        }
#pragma unroll
        for (int r2 = 0; r2 < 2; r2++)
            *(float4*)(Bs + (kk8 + r2 * 8) * 132 + (c32 << 2)) = bR[r2];
    };

    unsigned long long acc2[8][4];
#pragma unroll
    for (int i = 0; i < 8; i++)
#pragma unroll
        for (int j = 0; j < 4; j++) acc2[i][j] = 0ull;

    fetch(0);
#pragma unroll 1
    for (int t8 = 0; t8 < 8; t8++) {
        stage();
        __syncthreads();
        if (t8 < 7) fetch((t8 + 1) * 16);
#pragma unroll
        for (int kk = 0; kk < 16; kk++) {
            float4 a0 = *(const float4*)(As + kk * 132 + (trow << 2));
            float4 a1 = *(const float4*)(As + kk * 132 + (trow << 2) + 64);
            float4 b0 = *(const float4*)(Bs + kk * 132 + (tcol << 2));
            float4 b1 = *(const float4*)(Bs + kk * 132 + (tcol << 2) + 64);
            unsigned long long bp[4] = { pk2(b0.x, b0.y), pk2(b0.z, b0.w),
                                         pk2(b1.x, b1.y), pk2(b1.z, b1.w) };
            float av[8] = {a0.x, a0.y, a0.z, a0.w, a1.x, a1.y, a1.z, a1.w};
#pragma unroll
            for (int i = 0; i < 8; i++) {
                unsigned long long ap = pk2(av[i], av[i]);
#pragma unroll
                for (int j = 0; j < 4; j++) fma2(acc2[i][j], ap, bp[j]);
            }
        }
        __syncthreads();
    }

    float acc[8][8];
#pragma unroll
    for (int i = 0; i < 8; i++)
#pragma unroll
        for (int j = 0; j < 4; j++) upk2(acc[i][2 * j], acc[i][2 * j + 1], acc2[i][j]);

    int colL[8];
#pragma unroll
    for (int j = 0; j < 8; j++) colL[j] = (tcol << 2) + (j < 4 ? j : 60 + j);

    if (MODE == 0 || MODE == 3) {
        float* C = (MODE == 0) ? g_x : Cext;
#pragma unroll
        for (int i = 0; i < 8; i++) {
            int row = (trow << 2) + (i < 4 ? i : 60 + i);
            float* cp = C + (size_t)(m0 + row) * NC + n0 + (tcol << 2);
            *(float4*)cp        = make_float4(acc[i][0], acc[i][1], acc[i][2], acc[i][3]);
            *(float4*)(cp + 64) = make_float4(acc[i][4], acc[i][5], acc[i][6], acc[i][7]);
        }
    } else if (MODE == 1) {
        float bj[8], gj[8], tj[8];
#pragma unroll
        for (int j = 0; j < 8; j++) { bj[j] = bias[colL[j]]; gj[j] = gain[colL[j]]; tj[j] = beta[colL[j]]; }
#pragma unroll
        for (int i = 0; i < 8; i++) {
            float s = 0.f, s2 = 0.f;
#pragma unroll
            for (int j = 0; j < 8; j++) {
                float x = acc[i][j] + bj[j];
                acc[i][j] = x; s += x; s2 += x * x;
            }
#pragma unroll
            for (int off = 1; off < 16; off <<= 1) {
                s  += __shfl_xor_sync(0xffffffffu, s,  off, 16);
                s2 += __shfl_xor_sync(0xffffffffu, s2, off, 16);
            }
            float mu  = s * (1.f / 128.f);
            float var = s2 * (1.f / 128.f) - mu * mu;
            float rs  = rsqrtf(var + 1e-5f);
            float o[8];
#pragma unroll
            for (int j = 0; j < 8; j++) {
                float xn = (acc[i][j] - mu) * rs * gj[j] + tj[j];
                o[j] = 0.5f * xn * (1.f + erff(xn * 0.70710678118654752f));
            }
            int row = (trow << 2) + (i < 4 ? i : 60 + i);
            float* cp = g_hmid + (size_t)(m0 + row) * 128 + (tcol << 2);
            *(float4*)cp        = make_float4(o[0], o[1], o[2], o[3]);
            *(float4*)(cp + 64) = make_float4(o[4], o[5], o[6], o[7]);
        }
    } else { // MODE 2
        float bj[8], gj[8];
#pragma unroll
        for (int j = 0; j < 8; j++) { bj[j] = bias[n0 + colL[j]]; gj[j] = gain[n0 + colL[j]]; }
        float rsc[8];
#pragma unroll
        for (int i = 0; i < 8; i++) {
            float s = 0.f;
#pragma unroll
            for (int j = 0; j < 8; j++) {
                float x = (acc[i][j] + bj[j]) * gj[j];
                acc[i][j] = x; s += fabsf(x);
            }
#pragma unroll
            for (int off = 1; off < 16; off <<= 1)
                s += __shfl_xor_sync(0xffffffffu, s, off, 16);
            rsc[i] = 1.f / (s + 1e-8f);
        }
        float* dst = g_hT + (size_t)((m0 >> 13) * 2 + (n0 >> 7)) * 128 * 8192;
        int s0 = (m0 & 8191) + (trow << 2);
#pragma unroll
        for (int j = 0; j < 8; j++) {
            float* dp = dst + (size_t)colL[j] * 8192 + s0;
            *(float4*)dp = make_float4(acc[0][j] * rsc[0], acc[1][j] * rsc[1],
                                       acc[2][j] * rsc[2], acc[3][j] * rsc[3]);
            *(float4*)(dp + 64) = make_float4(acc[4][j] * rsc[4], acc[5][j] * rsc[5],
                                              acc[6][j] * rsc[6], acc[7][j] * rsc[7]);
        }
    }
}

// ---------------- FFT recurrence: radix-16 register stages ----------------
__global__ __launch_bounds__(1024, 1)
void k_fftrec(const float* __restrict__ Bp) {
    extern __shared__ float2 sh[];
    int b = blockIdx.x >> 7, d = blockIdx.x & 127;
    int t = threadIdx.x;
    const float* z = g_zc + (size_t)b * (8192 * 384) + (size_t)d * 24576;

    float vv[8];
#pragma unroll
    for (int k = 0; k < 8; k++) vv[k] = z[16384 + t + k * 1024];

    for (int it = 0; it < 2; it++) {
        const float* h = g_hT + (size_t)((b * 2 + it) * 128 + d) * 8192;

        // ===== F1: radix-16 (lg13+lg11), fused with pack+zero-pad =====
        {
            float2 x[16];
#pragma unroll
            for (int r = 0; r < 4; r++) {
                float2 x0 = make_float2(vv[r],     h[t + 1024 * r]);
                float2 x1 = make_float2(vv[r + 4], h[t + 1024 * r + 4096]);
                float2 W1 = g_tw[t + 1024 * r];
                float2 W2 = make_float2(W1.y, -W1.x);
                float2 W3 = cmul(W1, W1);
                float2 t02m = cmul(x0, W1);
                float2 t13m = cmul(x1, W2);
                x[r]      = cadd(x0, x1);
                x[r + 4]  = cmul(csub(x0, x1), W3);
                x[r + 8]  = cadd(t02m, t13m);
                x[r + 12] = cmul(csub(t02m, t13m), W3);
            }
            float2 Wl2 = g_tw[4 * t];
#pragma unroll
            for (int q = 0; q < 4; q++) fwd4(x[4 * q], x[4 * q + 1], x[4 * q + 2], x[4 * q + 3], Wl2);
#pragma unroll
            for (int r = 0; r < 16; r++) sh[PD(t + 1024 * r)] = x[r];
        }
        __syncthreads();

        // ===== F2: radix-16 (lg9+lg7): stride 64 in 1024-blocks =====
        {
            int blk = t >> 6, off = t & 63;
            int base = blk * 1024 + off;
            float2 x[16];
#pragma unroll
            for (int r = 0; r < 16; r++) x[r] = sh[PD(base + 64 * r)];
#pragma unroll
            for (int r = 0; r < 4; r++) fwd4(x[r], x[r + 4], x[r + 8], x[r + 12], g_tw[16 * off + 1024 * r]);
            float2 Wl2 = g_tw[64 * off];
#pragma unroll
            for (int q = 0; q < 4; q++) fwd4(x[4 * q], x[4 * q + 1], x[4 * q + 2], x[4 * q + 3], Wl2);
#pragma unroll
            for (int r = 0; r < 16; r++) sh[PD(base + 64 * r)] = x[r];
        }
        __syncthreads();

        // ===== F3: radix-16 (lg5+lg3): stride 4 in 64-blocks =====
        {
            int blk = t >> 2, off = t & 3;
            int base = blk * 64 + off;
            float2 x[16];
#pragma unroll
            for (int r = 0; r < 16; r++) x[r] = sh[PD(base + 4 * r)];
#pragma unroll
            for (int r = 0; r < 4; r++) fwd4(x[r], x[r + 4], x[r + 8], x[r + 12], g_tw[256 * off + 1024 * r]);
            float2 Wl2 = g_tw[1024 * off];
#pragma unroll
            for (int q = 0; q < 4; q++) fwd4(x[4 * q], x[4 * q + 1], x[4 * q + 2], x[4 * q + 3], Wl2);
#pragma unroll
            for (int r = 0; r < 16; r++) sh[PD(base + 4 * r)] = x[r];
        }
        __syncthreads();

        // ===== F4: radix-4 (lg1), trivial twiddles =====
#pragma unroll
        for (int k = 0; k < 4; k++) {
            int q4 = (t + 1024 * k) * 4;
            float2 y0 = sh[PD(q4)], y1 = sh[PD(q4 + 1)], y2 = sh[PD(q4 + 2)], y3 = sh[PD(q4 + 3)];
            fwd4(y0, y1, y2, y3, make_float2(1.f, 0.f));
            sh[PD(q4)] = y0; sh[PD(q4 + 1)] = y1; sh[PD(q4 + 2)] = y2; sh[PD(q4 + 3)] = y3;
        }
        __syncthreads();

        // ===== Spectral multiply (Hermitian split, bit-reversed) + I1 (lg0+lg2) =====
        {
            int e0 = t << 4;
            float2 x[16];
#pragma unroll
            for (int r = 0; r < 16; r++) x[r] = sh[PD(e0 + r)];
#pragma unroll
            for (int r = 0; r < 16; r++) {
                int p  = e0 + r;
                int kk = __brev(p) >> 18;
                int k2 = (16384 - kk) & 16383;
                int p2 = __brev(k2) >> 18;
                float2 Q = sh[PD(p2)];
                float2 P = x[r];
                float vx = 0.5f * (P.x + Q.x), vy = 0.5f * (P.y - Q.y);
                float hx = 0.5f * (P.y + Q.y), hy = 0.5f * (Q.x - P.x);
                x[r] = make_float2(vx * hx - vy * hy, vx * hy + vy * hx);
            }
            // I1 level A (lg0, w=1) on quads
#pragma unroll
            for (int q = 0; q < 4; q++) inv4(x[4 * q], x[4 * q + 1], x[4 * q + 2], x[4 * q + 3], make_float2(1.f, 0.f));
            // I1 level B (lg2)
#pragma unroll
            for (int r = 0; r < 4; r++) inv4(x[r], x[r + 4], x[r + 8], x[r + 12], g_tw[1024 * r]);
            __syncthreads();   // all spectral reads complete before overwrite
#pragma unroll
            for (int r = 0; r < 16; r++) sh[PD(e0 + r)] = x[r];
        }
        __syncthreads();

        // ===== I2: radix-16 (lg4+lg6): stride 16 in 256-blocks =====
        {
            int blk = t >> 4, off = t & 15;
            int base = blk * 256 + off;
            float2 x[16];
#pragma unroll
            for (int r = 0; r < 16; r++) x[r] = sh[PD(base + 16 * r)];
            float2 wA = g_tw[256 * off];
#pragma unroll
            for (int q = 0; q < 4; q++) inv4(x[4 * q], x[4 * q + 1], x[4 * q + 2], x[4 * q + 3], wA);
#pragma unroll
            for (int r = 0; r < 4; r++) inv4(x[r], x[r + 4], x[r + 8], x[r + 12], g_tw[64 * off + 1024 * r]);
#pragma unroll
            for (int r = 0; r < 16; r++) sh[PD(base + 16 * r)] = x[r];
        }
        __syncthreads();

        // ===== I3: radix-16 (lg8+lg10): stride 256 in 4096-blocks =====
        {
            int blk = t >> 8, off = t & 255;
            int base = blk * 4096 + off;
            float2 x[16];
#pragma unroll
            for (int r = 0; r < 16; r++) x[r] = sh[PD(base + 256 * r)];
            float2 wA = g_tw[16 * off];
#pragma unroll
            for (int q = 0; q < 4; q++) inv4(x[4 * q], x[4 * q + 1], x[4 * q + 2], x[4 * q + 3], wA);
#pragma unroll
            for (int r = 0; r < 4; r++) inv4(x[r], x[r + 4], x[r + 8], x[r + 12], g_tw[4 * off + 1024 * r]);
#pragma unroll
            for (int r = 0; r < 16; r++) sh[PD(base + 256 * r)] = x[r];
        }
        __syncthreads();

        // ===== I4: final radix-4 (lg12) fused with v-update (real parts, s<8192) =====
        {
            const float* zn = z + it * 8192;
            float Bn = Bp[it * 128 + d];
#pragma unroll
            for (int jj = 0; jj < 4; jj++) {
                int j = t + jj * 1024;
                float2 x0 = sh[PD(j)];
                float2 x1 = sh[PD(j + 4096)];
                float2 x2 = sh[PD(j + 8192)];
                float2 x3 = sh[PD(j + 12288)];
                float2 w   = g_tw[j];
                float2 cw2 = make_float2(w.x, -w.y);
                float2 cw1 = cmul(cw2, cw2);
                float2 cw3 = make_float2(-cw2.y, cw2.x);
                float2 b1 = cmul(x1, cw1);
                float2 b3 = cmul(x3, cw1);
                float2 u0 = cadd(x0, b1), u1 = csub(x0, b1);
                float2 u2 = cadd(x2, b3), u3 = csub(x2, b3);
                float y0x = u0.x + (u2.x * cw2.x - u2.y * cw2.y);
                float y1x = u1.x + (u3.x * cw3.x - u3.y * cw3.y);
                vv[jj]     = zn[j]        * (y0x * SCALE_U + Bn * vv[jj]);
                vv[jj + 4] = zn[j + 4096] * (y1x * SCALE_U + Bn * vv[jj + 4]);
            }
        }
        __syncthreads();
    }
    float* vo = g_vT + (size_t)(b * 128 + d) * 8192;
#pragma unroll
    for (int k = 0; k < 8; k++) vo[t + k * 1024] = vv[k];
}

extern "C" void kernel_launch(void* const* d_in, const int* in_sizes, int n_in,
                              void* d_out, int out_size) {
    const float* emb = (const float*)d_in[0];
    const float* Wp  = (const float*)d_in[1];
    const float* cw  = (const float*)d_in[2];
    const float* cb  = (const float*)d_in[3];
    const float* W1  = (const float*)d_in[4];
    const float* b1  = (const float*)d_in[5];
    const float* lng = (const float*)d_in[6];
    const float* lnb = (const float*)d_in[7];
    const float* W2  = (const float*)d_in[8];
    const float* b2  = (const float*)d_in[9];
    const float* ffs = (const float*)d_in[10];
    const float* op  = (const float*)d_in[11];
    const float* Bp  = (const float*)d_in[12];
    const int*   pos = (const int*)d_in[13];
    float* out = (float*)d_out;

    const int FFT_SMEM = 139776;  // PD(16383)+1 float2, rounded up
    cudaFuncSetAttribute(k_fftrec, cudaFuncAttributeMaxDynamicSharedMemorySize, FFT_SMEM);

    k_twiddle<<<32, 256>>>();
    k_sgemm<0><<<dim3(256, 3), 256>>>(emb, Wp, nullptr, nullptr, nullptr, nullptr);
    k_conv<<<12288, 256>>>(cw, cb);
    k_rope<<<8192, 256>>>(emb, pos);
    k_sgemm<1><<<dim3(256, 1), 256>>>(nullptr, W1, b1, lng, lnb, nullptr);
    k_sgemm<2><<<dim3(256, 2), 256>>>(nullptr, W2, b2, ffs, nullptr, nullptr);
    k_fftrec<<<512, 1024, FFT_SMEM>>>(Bp);
    k_sgemm<3><<<dim3(256, 1), 256>>>(nullptr, op, nullptr, nullptr, nullptr, out);
}

// round 8
// speedup vs baseline: 1.2700x; 1.1424x over previous
#include <cuda_runtime.h>
#include <cuda_bf16.h>
#include <math.h>
#include <stdint.h>

#define Mr 32768
#define GDc 384
#define NFFT 16384
#define HALFN 8192
#define SCALE_U (1.0f / (16384.0f * 16384.0f))

// padded smem index for FFT: conflict-free for strides {1,4,16,64,256,1024,4096}
__device__ __forceinline__ int PD(int e) { return e + (e >> 4) + (e >> 8); }

__device__ __forceinline__ float2 cmul(float2 a, float2 b) {
    return make_float2(a.x * b.x - a.y * b.y, a.x * b.y + a.y * b.x);
}
__device__ __forceinline__ float2 cadd(float2 a, float2 b) { return make_float2(a.x + b.x, a.y + b.y); }
__device__ __forceinline__ float2 csub(float2 a, float2 b) { return make_float2(a.x - b.x, a.y - b.y); }

__device__ __forceinline__ void fwd4(float2& x0, float2& x1, float2& x2, float2& x3, float2 W1) {
    float2 W2 = make_float2(W1.y, -W1.x);
    float2 W3 = cmul(W1, W1);
    float2 t02p = cadd(x0, x2), t02m = cmul(csub(x0, x2), W1);
    float2 t13p = cadd(x1, x3), t13m = cmul(csub(x1, x3), W2);
    x0 = cadd(t02p, t13p);
    x1 = cmul(csub(t02p, t13p), W3);
    x2 = cadd(t02m, t13m);
    x3 = cmul(csub(t02m, t13m), W3);
}
__device__ __forceinline__ void inv4(float2& x0, float2& x1, float2& x2, float2& x3, float2 w) {
    float2 cw2 = make_float2(w.x, -w.y);
    float2 cw1 = cmul(cw2, cw2);
    float2 cw3 = make_float2(-cw2.y, cw2.x);
    float2 b1 = cmul(x1, cw1), b3 = cmul(x3, cw1);
    float2 u0 = cadd(x0, b1), u1 = csub(x0, b1);
    float2 u2 = cadd(x2, b3), u3 = csub(x2, b3);
    float2 c2 = cmul(u2, cw2), c3 = cmul(u3, cw3);
    x0 = cadd(u0, c2); x2 = csub(u0, c2);
    x1 = cadd(u1, c3); x3 = csub(u1, c3);
}

// ---- tensor-core helpers ----
__device__ __forceinline__ void ldm4(uint32_t* r, const void* p) {
    uint32_t a = (uint32_t)__cvta_generic_to_shared(p);
    asm volatile("ldmatrix.sync.aligned.m8n8.x4.shared.b16 {%0,%1,%2,%3}, [%4];"
                 : "=r"(r[0]), "=r"(r[1]), "=r"(r[2]), "=r"(r[3]) : "r"(a));
}
__device__ __forceinline__ void ldm4t(uint32_t* r, const void* p) {
    uint32_t a = (uint32_t)__cvta_generic_to_shared(p);
    asm volatile("ldmatrix.sync.aligned.m8n8.x4.trans.shared.b16 {%0,%1,%2,%3}, [%4];"
                 : "=r"(r[0]), "=r"(r[1]), "=r"(r[2]), "=r"(r[3]) : "r"(a));
}
__device__ __forceinline__ void mmabf(float* c, const uint32_t* a, const uint32_t* b) {
    asm volatile("mma.sync.aligned.m16n8k16.row.col.f32.bf16.bf16.f32 "
                 "{%0,%1,%2,%3}, {%4,%5,%6,%7}, {%8,%9}, {%0,%1,%2,%3};"
                 : "+f"(c[0]), "+f"(c[1]), "+f"(c[2]), "+f"(c[3])
                 : "r"(a[0]), "r"(a[1]), "r"(a[2]), "r"(a[3]), "r"(b[0]), "r"(b[1]));
}
// split two floats into packed bf16 hi / lo pairs
__device__ __forceinline__ void split2(float a, float b, uint32_t& hi, uint32_t& lo) {
    __nv_bfloat16 ah = __float2bfloat16_rn(a), bh = __float2bfloat16_rn(b);
    float ar = a - __bfloat162float(ah), br = b - __bfloat162float(bh);
    __nv_bfloat16 al = __float2bfloat16_rn(ar), bl = __float2bfloat16_rn(br);
    hi = (uint32_t)__bfloat16_as_ushort(ah) | ((uint32_t)__bfloat16_as_ushort(bh) << 16);
    lo = (uint32_t)__bfloat16_as_ushort(al) | ((uint32_t)__bfloat16_as_ushort(bl) << 16);
}

// ---------------- scratch (device globals) ----------------
__device__ float  g_x   [(long long)Mr * GDc];
__device__ float  g_zc  [(long long)Mr * GDc];
__device__ float  g_t   [(long long)Mr * 128];
__device__ float  g_hmid[(long long)Mr * 128];
__device__ float  g_hT  [(long long)4 * 2 * 128 * 8192];
__device__ float  g_vT  [(long long)4 * 128 * 8192];
__device__ float2 g_tw  [HALFN];

// ---------------- twiddles ----------------
__global__ void k_twiddle() {
    int k = blockIdx.x * 256 + threadIdx.x;
    double a = -2.0 * 3.14159265358979323846 * (double)k / (double)NFFT;
    g_tw[k] = make_float2((float)cos(a), (float)sin(a));
}

// ---------------- RoPE ----------------
__global__ void k_rope(const float* __restrict__ emb, const int* __restrict__ pos) {
    int idx = blockIdx.x * blockDim.x + threadIdx.x;
    if (idx >= Mr * 64) return;
    int j  = idx & 63;
    int bs = idx >> 6;
    float theta = exp2f(-(float)j * 0.20762050593046015f);
    float ang = (float)pos[bs] * theta;
    float sa, ca; sincosf(ang, &sa, &ca);
    float2 xv = *(const float2*)(emb + (size_t)bs * 128 + 2 * j);
    float2 o;
    o.x = xv.x * ca - xv.y * sa;
    o.y = xv.x * sa + xv.y * ca;
    *(float2*)(g_t + (size_t)bs * 128 + 2 * j) = o;
}

// ---------------- depthwise conv K=3 along S ----------------
__global__ __launch_bounds__(256)
void k_conv(const float* __restrict__ w, const float* __restrict__ bias) {
    __shared__ float ws[3 * 384];
    __shared__ float bs_[384];
    int t = threadIdx.x;
    for (int i = t; i < 384; i += 256) bs_[i] = bias[i];
    for (int i = t; i < 1152; i += 256) ws[i] = w[i];
    __syncthreads();

    int idx = blockIdx.x * 256 + t;
    if (idx >= Mr * 96) return;
    int cg = idx % 96;
    int bs = idx / 96;
    int s  = bs & 8191;
    int c  = cg * 4;
    const float* xp = g_x + (size_t)bs * GDc + c;
    float4 x1 = *(const float4*)xp;
    float4 acc;
    acc.x = bs_[c + 0] + x1.x * ws[(c + 0) * 3 + 1];
    acc.y = bs_[c + 1] + x1.y * ws[(c + 1) * 3 + 1];
    acc.z = bs_[c + 2] + x1.z * ws[(c + 2) * 3 + 1];
    acc.w = bs_[c + 3] + x1.w * ws[(c + 3) * 3 + 1];
    if (s > 0) {
        float4 x0 = *(const float4*)(xp - GDc);
        acc.x += x0.x * ws[(c + 0) * 3];
        acc.y += x0.y * ws[(c + 1) * 3];
        acc.z += x0.z * ws[(c + 2) * 3];
        acc.w += x0.w * ws[(c + 3) * 3];
    }
    if (s < 8191) {
        float4 x2 = *(const float4*)(xp + GDc);
        acc.x += x2.x * ws[(c + 0) * 3 + 2];
        acc.y += x2.y * ws[(c + 1) * 3 + 2];
        acc.z += x2.z * ws[(c + 2) * 3 + 2];
        acc.w += x2.w * ws[(c + 3) * 3 + 2];
    }
    *(float4*)(g_zc + (size_t)bs * GDc + c) = acc;
}

// ---------------- tensor-core GEMMs (bf16 3-term split) ----------------
// MODE 0: g_x = emb @ W_proj                       (NC=384)
// MODE 1: g_hmid = gelu(LN(g_t @ W1 + b1))         (NC=128)
// MODE 2: g_hT   = L1norm((g_hmid@W2+b2)*ffs), T   (NC=256)
// MODE 3: out    = v^T @ out_proj  (A col-major)   (NC=128)
// stage layout (bytes): AH=0, AL=6144, BH=12288, BL=16896, stride 21504
#define STG 21504
#define AHo 0
#define ALo 6144
#define BHo 12288
#define BLo 16896

template<int MODE>
__global__ __launch_bounds__(256, 2)
void k_mma(const float* __restrict__ Aext, const float* __restrict__ W,
           const float* __restrict__ bias, const float* __restrict__ gain,
           const float* __restrict__ beta, float* __restrict__ Cext)
{
    constexpr int  NC   = (MODE == 0) ? 384 : (MODE == 2) ? 256 : 128;
    constexpr bool KMAJ = (MODE == 3);
    extern __shared__ char dsm[];

    const int tid = threadIdx.x;
    const int m0  = blockIdx.x * 128;
    const int n0  = blockIdx.y * 128;
    const int wid = tid >> 5, lid = tid & 31;
    const int wm  = wid >> 2, wn = wid & 3;

    const float* A;
    if      (MODE == 0) A = Aext;
    else if (MODE == 1) A = g_t;
    else if (MODE == 2) A = g_hmid;
    else                A = g_vT + (size_t)(m0 >> 13) * (128 * 8192) + (m0 & 8191);

    float acc[4][4][4];
#pragma unroll
    for (int mi = 0; mi < 4; mi++)
#pragma unroll
        for (int ni = 0; ni < 4; ni++)
#pragma unroll
            for (int q = 0; q < 4; q++) acc[mi][ni][q] = 0.f;

    // staging register buffers
    float4 ra0, ra1, rb0, rb1;
    const int arow = tid >> 1, akh = (tid & 1) * 8;      // A [m][k] staging
    const int krow = tid >> 4, nq8 = (tid & 15) * 8;     // B / KMAJ-A staging

    auto fetch = [&](int kt) {
        if (KMAJ) {
            const float* ap = A + (size_t)(kt + krow) * 8192 + nq8;
            ra0 = *(const float4*)ap; ra1 = *(const float4*)(ap + 4);
        } else {
            const float* ap = A + (size_t)(m0 + arow) * 128 + kt + akh;
            ra0 = *(const float4*)ap; ra1 = *(const float4*)(ap + 4);
        }
        const float* bp = W + (size_t)(kt + krow) * NC + n0 + nq8;
        rb0 = *(const float4*)bp; rb1 = *(const float4*)(bp + 4);
    };
    auto stage = [&](int s) {
        char* sb = dsm + s * STG;
        uint32_t h0, l0, h1, l1, h2, l2, h3, l3;
        split2(ra0.x, ra0.y, h0, l0); split2(ra0.z, ra0.w, h1, l1);
        split2(ra1.x, ra1.y, h2, l2); split2(ra1.z, ra1.w, h3, l3);
        if (KMAJ) {
            uint32_t* pH = (uint32_t*)(sb + AHo + krow * 272 + nq8 * 2);
            uint32_t* pL = (uint32_t*)(sb + ALo + krow * 272 + nq8 * 2);
            pH[0] = h0; pH[1] = h1; pH[2] = h2; pH[3] = h3;
            pL[0] = l0; pL[1] = l1; pL[2] = l2; pL[3] = l3;
        } else {
            uint32_t* pH = (uint32_t*)(sb + AHo + arow * 48 + akh * 2);
            uint32_t* pL = (uint32_t*)(sb + ALo + arow * 48 + akh * 2);
            pH[0] = h0; pH[1] = h1; pH[2] = h2; pH[3] = h3;
            pL[0] = l0; pL[1] = l1; pL[2] = l2; pL[3] = l3;
        }
        split2(rb0.x, rb0.y, h0, l0); split2(rb0.z, rb0.w, h1, l1);
        split2(rb1.x, rb1.y, h2, l2); split2(rb1.z, rb1.w, h3, l3);
        uint32_t* pH = (uint32_t*)(sb + BHo + krow * 272 + nq8 * 2);
        uint32_t* pL = (uint32_t*)(sb + BLo + krow * 272 + nq8 * 2);
        pH[0] = h0; pH[1] = h1; pH[2] = h2; pH[3] = h3;
        pL[0] = l0; pL[1] = l1; pL[2] = l2; pL[3] = l3;
    };

    auto compute = [&](int s) {
        char* sb = dsm + s * STG;
        uint32_t Ah[4][4], Al[4][4];
        if (!KMAJ) {
            int ar = wm * 64 + (lid & 15);
            int ac = ((lid >> 4) & 1) * 16;
#pragma unroll
            for (int mi = 0; mi < 4; mi++) {
                ldm4(Ah[mi], sb + AHo + (ar + mi * 16) * 48 + ac);
                ldm4(Al[mi], sb + ALo + (ar + mi * 16) * 48 + ac);
            }
        } else {
            int kr = ((lid >> 4) & 1) * 8 + (lid & 7);
            int mc = wm * 64 + ((lid >> 3) & 1) * 8;
#pragma unroll
            for (int mi = 0; mi < 4; mi++) {
                ldm4t(Ah[mi], sb + AHo + kr * 272 + (mc + mi * 16) * 2);
                ldm4t(Al[mi], sb + ALo + kr * 272 + (mc + mi * 16) * 2);
            }
        }
        int kr = ((lid >> 3) & 1) * 8 + (lid & 7);
        int ncb = wn * 32 + ((lid >> 4) & 1) * 8;
#pragma unroll
        for (int p = 0; p < 2; p++) {
            uint32_t Bh[4], Bl[4];
            ldm4t(Bh, sb + BHo + kr * 272 + (ncb + p * 16) * 2);
            ldm4t(Bl, sb + BLo + kr * 272 + (ncb + p * 16) * 2);
#pragma unroll
            for (int q = 0; q < 2; q++) {
                int ni = p * 2 + q;
#pragma unroll
                for (int mi = 0; mi < 4; mi++) {
                    mmabf(acc[mi][ni], Ah[mi], Bh + 2 * q);
                    mmabf(acc[mi][ni], Ah[mi], Bl + 2 * q);
                    mmabf(acc[mi][ni], Al[mi], Bh + 2 * q);
                }
            }
        }
    };

    fetch(0); stage(0);
    __syncthreads();
#pragma unroll 1
    for (int c = 0; c < 8; c++) {
        if (c < 7) fetch((c + 1) * 16);
        compute(c & 1);
        if (c < 7) stage((c + 1) & 1);
        __syncthreads();
    }

    // ---------------- epilogues ----------------
    if (MODE == 0 || MODE == 3) {
        float* C = (MODE == 0) ? g_x : Cext;
#pragma unroll
        for (int mi = 0; mi < 4; mi++)
#pragma unroll
            for (int ni = 0; ni < 4; ni++) {
                int r0 = m0 + wm * 64 + mi * 16 + (lid >> 2);
                int cc = n0 + wn * 32 + ni * 8 + 2 * (lid & 3);
                *(float2*)(C + (size_t)r0 * NC + cc)       = make_float2(acc[mi][ni][0], acc[mi][ni][1]);
                *(float2*)(C + (size_t)(r0 + 8) * NC + cc) = make_float2(acc[mi][ni][2], acc[mi][ni][3]);
            }
        return;
    }

    // MODE 1 / 2: dump fragments to smem [128][129]
    float* Ep = (float*)dsm;
    __syncthreads();
#pragma unroll
    for (int mi = 0; mi < 4; mi++)
#pragma unroll
        for (int ni = 0; ni < 4; ni++) {
            int r0 = wm * 64 + mi * 16 + (lid >> 2);
            int cc = wn * 32 + ni * 8 + 2 * (lid & 3);
            Ep[r0 * 129 + cc]           = acc[mi][ni][0];
            Ep[r0 * 129 + cc + 1]       = acc[mi][ni][1];
            Ep[(r0 + 8) * 129 + cc]     = acc[mi][ni][2];
            Ep[(r0 + 8) * 129 + cc + 1] = acc[mi][ni][3];
        }
    __syncthreads();

    int row = tid >> 1, half = tid & 1;
    float* rp = Ep + row * 129 + half * 64;

    if (MODE == 1) {
        float s = 0.f, s2 = 0.f;
#pragma unroll 4
        for (int i = 0; i < 64; i++) {
            float x = rp[i] + bias[half * 64 + i];
            s += x; s2 += x * x;
        }
        s  += __shfl_xor_sync(0xffffffffu, s,  1);
        s2 += __shfl_xor_sync(0xffffffffu, s2, 1);
        float mu  = s * (1.f / 128.f);
        float var = s2 * (1.f / 128.f) - mu * mu;
        float rs  = rsqrtf(var + 1e-5f);
        float* op = g_hmid + (size_t)(m0 + row) * 128 + half * 64;
#pragma unroll 1
        for (int i = 0; i < 16; i++) {
            float4 o;
            float* po = (float*)&o;
#pragma unroll
            for (int j = 0; j < 4; j++) {
                int cc = half * 64 + i * 4 + j;
                float x  = rp[i * 4 + j] + bias[cc];
                float xn = (x - mu) * rs * gain[cc] + beta[cc];
                po[j] = 0.5f * xn * (1.f + erff(xn * 0.70710678118654752f));
            }
            *(float4*)(op + i * 4) = o;
        }
    } else { // MODE 2
        float s = 0.f;
#pragma unroll 4
        for (int i = 0; i < 64; i++) {
            int gc = n0 + half * 64 + i;
            float x = (rp[i] + bias[gc]) * gain[gc];
            s += fabsf(x);
        }
        s += __shfl_xor_sync(0xffffffffu, s, 1);
        float rsc = 1.f / (s + 1e-8f);
#pragma unroll 4
        for (int i = 0; i < 64; i++) {
            int gc = n0 + half * 64 + i;
            rp[i] = (rp[i] + bias[gc]) * gain[gc] * rsc;
        }
        __syncthreads();
        // transposed store: g_hT[b, n, d, s]
        float* dst = g_hT + (size_t)((m0 >> 13) * 2 + (n0 >> 7)) * (128 * 8192) + (m0 & 8191);
#pragma unroll 1
        for (int ccs = 0; ccs < 16; ccs++) {
            int cc = wid * 16 + ccs;
            float* dp = dst + (size_t)cc * 8192;
#pragma unroll
            for (int sq = 0; sq < 4; sq++) {
                dp[sq * 32 + lid] = Ep[(sq * 32 + lid) * 129 + cc];
            }
        }
    }
}

// ---------------- FFT recurrence: radix-16 register stages ----------------
__global__ __launch_bounds__(1024, 1)
void k_fftrec(const float* __restrict__ Bp) {
    extern __shared__ float2 sh[];
    int b = blockIdx.x >> 7, d = blockIdx.x & 127;
    int t = threadIdx.x;
    const float* z = g_zc + (size_t)b * (8192 * 384) + (size_t)d * 24576;

    float vv[8];
#pragma unroll
    for (int k = 0; k < 8; k++) vv[k] = z[16384 + t + k * 1024];

    for (int it = 0; it < 2; it++) {
        const float* h = g_hT + (size_t)((b * 2 + it) * 128 + d) * 8192;

        // F1: radix-16 (lg13+lg11), fused with pack+zero-pad
        {
            float2 x[16];
#pragma unroll
            for (int r = 0; r < 4; r++) {
                float2 x0 = make_float2(vv[r],     h[t + 1024 * r]);
                float2 x1 = make_float2(vv[r + 4], h[t + 1024 * r + 4096]);
                float2 W1 = g_tw[t + 1024 * r];
                float2 W2 = make_float2(W1.y, -W1.x);
                float2 W3 = cmul(W1, W1);
                float2 t02m = cmul(x0, W1);
                float2 t13m = cmul(x1, W2);
                x[r]      = cadd(x0, x1);
                x[r + 4]  = cmul(csub(x0, x1), W3);
                x[r + 8]  = cadd(t02m, t13m);
                x[r + 12] = cmul(csub(t02m, t13m), W3);
            }
            float2 Wl2 = g_tw[4 * t];
#pragma unroll
            for (int q = 0; q < 4; q++) fwd4(x[4 * q], x[4 * q + 1], x[4 * q + 2], x[4 * q + 3], Wl2);
#pragma unroll
            for (int r = 0; r < 16; r++) sh[PD(t + 1024 * r)] = x[r];
        }
        __syncthreads();

        // F2: radix-16 (lg9+lg7)
        {
            int blk = t >> 6, off = t & 63;
            int base = blk * 1024 + off;
            float2 x[16];
#pragma unroll
            for (int r = 0; r < 16; r++) x[r] = sh[PD(base + 64 * r)];
#pragma unroll
            for (int r = 0; r < 4; r++) fwd4(x[r], x[r + 4], x[r + 8], x[r + 12], g_tw[16 * off + 1024 * r]);
            float2 Wl2 = g_tw[64 * off];
#pragma unroll
            for (int q = 0; q < 4; q++) fwd4(x[4 * q], x[4 * q + 1], x[4 * q + 2], x[4 * q + 3], Wl2);
#pragma unroll
            for (int r = 0; r < 16; r++) sh[PD(base + 64 * r)] = x[r];
        }
        __syncthreads();

        // F3: radix-16 (lg5+lg3)
        {
            int blk = t >> 2, off = t & 3;
            int base = blk * 64 + off;
            float2 x[16];
#pragma unroll
            for (int r = 0; r < 16; r++) x[r] = sh[PD(base + 4 * r)];
#pragma unroll
            for (int r = 0; r < 4; r++) fwd4(x[r], x[r + 4], x[r + 8], x[r + 12], g_tw[256 * off + 1024 * r]);
            float2 Wl2 = g_tw[1024 * off];
#pragma unroll
            for (int q = 0; q < 4; q++) fwd4(x[4 * q], x[4 * q + 1], x[4 * q + 2], x[4 * q + 3], Wl2);
#pragma unroll
            for (int r = 0; r < 16; r++) sh[PD(base + 4 * r)] = x[r];
        }
        __syncthreads();

        // F4: radix-4 (lg1)
#pragma unroll
        for (int k = 0; k < 4; k++) {
            int q4 = (t + 1024 * k) * 4;
            float2 y0 = sh[PD(q4)], y1 = sh[PD(q4 + 1)], y2 = sh[PD(q4 + 2)], y3 = sh[PD(q4 + 3)];
            fwd4(y0, y1, y2, y3, make_float2(1.f, 0.f));
            sh[PD(q4)] = y0; sh[PD(q4 + 1)] = y1; sh[PD(q4 + 2)] = y2; sh[PD(q4 + 3)] = y3;
        }
        __syncthreads();

        // spectral multiply + I1 (lg0+lg2)
        {
            int e0 = t << 4;
            float2 x[16];
#pragma unroll
            for (int r = 0; r < 16; r++) x[r] = sh[PD(e0 + r)];
#pragma unroll
            for (int r = 0; r < 16; r++) {
                int p  = e0 + r;
                int kk = __brev(p) >> 18;
                int k2 = (16384 - kk) & 16383;
                int p2 = __brev(k2) >> 18;
                float2 Q = sh[PD(p2)];
                float2 P = x[r];
                float vx = 0.5f * (P.x + Q.x), vy = 0.5f * (P.y - Q.y);
                float hx = 0.5f * (P.y + Q.y), hy = 0.5f * (Q.x - P.x);
                x[r] = make_float2(vx * hx - vy * hy, vx * hy + vy * hx);
            }
#pragma unroll
            for (int q = 0; q < 4; q++) inv4(x[4 * q], x[4 * q + 1], x[4 * q + 2], x[4 * q + 3], make_float2(1.f, 0.f));
#pragma unroll
            for (int r = 0; r < 4; r++) inv4(x[r], x[r + 4], x[r + 8], x[r + 12], g_tw[1024 * r]);
            __syncthreads();
#pragma unroll
            for (int r = 0; r < 16; r++) sh[PD(e0 + r)] = x[r];
        }
        __syncthreads();

        // I2: radix-16 (lg4+lg6)
        {
            int blk = t >> 4, off = t & 15;
            int base = blk * 256 + off;
            float2 x[16];
#pragma unroll
            for (int r = 0; r < 16; r++) x[r] = sh[PD(base + 16 * r)];
            float2 wA = g_tw[256 * off];
#pragma unroll
            for (int q = 0; q < 4; q++) inv4(x[4 * q], x[4 * q + 1], x[4 * q + 2], x[4 * q + 3], wA);
#pragma unroll
            for (int r = 0; r < 4; r++) inv4(x[r], x[r + 4], x[r + 8], x[r + 12], g_tw[64 * off + 1024 * r]);
#pragma unroll
            for (int r = 0; r < 16; r++) sh[PD(base + 16 * r)] = x[r];
        }
        __syncthreads();

        // I3: radix-16 (lg8+lg10)
        {
            int blk = t >> 8, off = t & 255;
            int base = blk * 4096 + off;
            float2 x[16];
#pragma unroll
            for (int r = 0; r < 16; r++) x[r] = sh[PD(base + 256 * r)];
            float2 wA = g_tw[16 * off];
#pragma unroll
            for (int q = 0; q < 4; q++) inv4(x[4 * q], x[4 * q + 1], x[4 * q + 2], x[4 * q + 3], wA);
#pragma unroll
            for (int r = 0; r < 4; r++) inv4(x[r], x[r + 4], x[r + 8], x[r + 12], g_tw[4 * off + 1024 * r]);
#pragma unroll
            for (int r = 0; r < 16; r++) sh[PD(base + 256 * r)] = x[r];
        }
        __syncthreads();

        // I4: final radix-4 (lg12) fused with v-update
        {
            const float* zn = z + it * 8192;
            float Bn = Bp[it * 128 + d];
#pragma unroll
            for (int jj = 0; jj < 4; jj++) {
                int j = t + jj * 1024;
                float2 x0 = sh[PD(j)];
                float2 x1 = sh[PD(j + 4096)];
                float2 x2 = sh[PD(j + 8192)];
                float2 x3 = sh[PD(j + 12288)];
                float2 w   = g_tw[j];
                float2 cw2 = make_float2(w.x, -w.y);
                float2 cw1 = cmul(cw2, cw2);
                float2 cw3 = make_float2(-cw2.y, cw2.x);
                float2 b1 = cmul(x1, cw1);
                float2 b3 = cmul(x3, cw1);
                float2 u0 = cadd(x0, b1), u1 = csub(x0, b1);
                float2 u2 = cadd(x2, b3), u3 = csub(x2, b3);
                float y0x = u0.x + (u2.x * cw2.x - u2.y * cw2.y);
                float y1x = u1.x + (u3.x * cw3.x - u3.y * cw3.y);
                vv[jj]     = zn[j]        * (y0x * SCALE_U + Bn * vv[jj]);
                vv[jj + 4] = zn[j + 4096] * (y1x * SCALE_U + Bn * vv[jj + 4]);
            }
        }
        __syncthreads();
    }
    float* vo = g_vT + (size_t)(b * 128 + d) * 8192;
#pragma unroll
    for (int k = 0; k < 8; k++) vo[t + k * 1024] = vv[k];
}

extern "C" void kernel_launch(void* const* d_in, const int* in_sizes, int n_in,
                              void* d_out, int out_size) {
    const float* emb = (const float*)d_in[0];
    const float* Wp  = (const float*)d_in[1];
    const float* cw  = (const float*)d_in[2];
    const float* cb  = (const float*)d_in[3];
    const float* W1  = (const float*)d_in[4];
    const float* b1  = (const float*)d_in[5];
    const float* lng = (const float*)d_in[6];
    const float* lnb = (const float*)d_in[7];
    const float* W2  = (const float*)d_in[8];
    const float* b2  = (const float*)d_in[9];
    const float* ffs = (const float*)d_in[10];
    const float* op  = (const float*)d_in[11];
    const float* Bp  = (const float*)d_in[12];
    const int*   pos = (const int*)d_in[13];
    float* out = (float*)d_out;

    const int FFT_SMEM  = 139776;
    const int MMA_SMEM_SMALL = 2 * STG;      // 43008 (modes 0,3)
    const int MMA_SMEM_BIG   = 128 * 129 * 4; // 66048 (modes 1,2)
    cudaFuncSetAttribute(k_fftrec, cudaFuncAttributeMaxDynamicSharedMemorySize, FFT_SMEM);
    cudaFuncSetAttribute(k_mma<0>, cudaFuncAttributeMaxDynamicSharedMemorySize, MMA_SMEM_SMALL);
    cudaFuncSetAttribute(k_mma<1>, cudaFuncAttributeMaxDynamicSharedMemorySize, MMA_SMEM_BIG);
    cudaFuncSetAttribute(k_mma<2>, cudaFuncAttributeMaxDynamicSharedMemorySize, MMA_SMEM_BIG);
    cudaFuncSetAttribute(k_mma<3>, cudaFuncAttributeMaxDynamicSharedMemorySize, MMA_SMEM_SMALL);

    k_twiddle<<<32, 256>>>();
    k_mma<0><<<dim3(256, 3), 256, MMA_SMEM_SMALL>>>(emb, Wp, nullptr, nullptr, nullptr, nullptr);
    k_conv<<<12288, 256>>>(cw, cb);
    k_rope<<<8192, 256>>>(emb, pos);
    k_mma<1><<<dim3(256, 1), 256, MMA_SMEM_BIG>>>(nullptr, W1, b1, lng, lnb, nullptr);
    k_mma<2><<<dim3(256, 2), 256, MMA_SMEM_BIG>>>(nullptr, W2, b2, ffs, nullptr, nullptr);
    k_fftrec<<<512, 1024, FFT_SMEM>>>(Bp);
    k_mma<3><<<dim3(256, 1), 256, MMA_SMEM_SMALL>>>(nullptr, op, nullptr, nullptr, nullptr, out);
}

// round 10
// speedup vs baseline: 1.2973x; 1.0214x over previous
#include <cuda_runtime.h>
#include <cuda_bf16.h>
#include <math.h>
#include <stdint.h>

#define Mr 32768
#define GDc 384
#define NFFT 16384
#define HALFN 8192
#define SCALE_U (1.0f / (16384.0f * 16384.0f))

// padded smem index for FFT: conflict-free for strides {1,4,16,64,256,1024,4096}
__device__ __forceinline__ int PD(int e) { return e + (e >> 4) + (e >> 8); }

__device__ __forceinline__ float2 cmul(float2 a, float2 b) {
    return make_float2(a.x * b.x - a.y * b.y, a.x * b.y + a.y * b.x);
}
__device__ __forceinline__ float2 cadd(float2 a, float2 b) { return make_float2(a.x + b.x, a.y + b.y); }
__device__ __forceinline__ float2 csub(float2 a, float2 b) { return make_float2(a.x - b.x, a.y - b.y); }

__device__ __forceinline__ void fwd4(float2& x0, float2& x1, float2& x2, float2& x3, float2 W1) {
    float2 W2 = make_float2(W1.y, -W1.x);
    float2 W3 = cmul(W1, W1);
    float2 t02p = cadd(x0, x2), t02m = cmul(csub(x0, x2), W1);
    float2 t13p = cadd(x1, x3), t13m = cmul(csub(x1, x3), W2);
    x0 = cadd(t02p, t13p);
    x1 = cmul(csub(t02p, t13p), W3);
    x2 = cadd(t02m, t13m);
    x3 = cmul(csub(t02m, t13m), W3);
}
__device__ __forceinline__ void inv4(float2& x0, float2& x1, float2& x2, float2& x3, float2 w) {
    float2 cw2 = make_float2(w.x, -w.y);
    float2 cw1 = cmul(cw2, cw2);
    float2 cw3 = make_float2(-cw2.y, cw2.x);
    float2 b1 = cmul(x1, cw1), b3 = cmul(x3, cw1);
    float2 u0 = cadd(x0, b1), u1 = csub(x0, b1);
    float2 u2 = cadd(x2, b3), u3 = csub(x2, b3);
    float2 c2 = cmul(u2, cw2), c3 = cmul(u3, cw3);
    x0 = cadd(u0, c2); x2 = csub(u0, c2);
    x1 = cadd(u1, c3); x3 = csub(u1, c3);
}

// ---- tensor-core helpers ----
__device__ __forceinline__ void ldm4(uint32_t* r, const void* p) {
    uint32_t a = (uint32_t)__cvta_generic_to_shared(p);
    asm volatile("ldmatrix.sync.aligned.m8n8.x4.shared.b16 {%0,%1,%2,%3}, [%4];"
                 : "=r"(r[0]), "=r"(r[1]), "=r"(r[2]), "=r"(r[3]) : "r"(a));
}
__device__ __forceinline__ void ldm4t(uint32_t* r, const void* p) {
    uint32_t a = (uint32_t)__cvta_generic_to_shared(p);
    asm volatile("ldmatrix.sync.aligned.m8n8.x4.trans.shared.b16 {%0,%1,%2,%3}, [%4];"
                 : "=r"(r[0]), "=r"(r[1]), "=r"(r[2]), "=r"(r[3]) : "r"(a));
}
__device__ __forceinline__ void mmabf(float* c, const uint32_t* a, const uint32_t* b) {
    asm volatile("mma.sync.aligned.m16n8k16.row.col.f32.bf16.bf16.f32 "
                 "{%0,%1,%2,%3}, {%4,%5,%6,%7}, {%8,%9}, {%0,%1,%2,%3};"
                 : "+f"(c[0]), "+f"(c[1]), "+f"(c[2]), "+f"(c[3])
                 : "r"(a[0]), "r"(a[1]), "r"(a[2]), "r"(a[3]), "r"(b[0]), "r"(b[1]));
}
__device__ __forceinline__ void split2(float a, float b, uint32_t& hi, uint32_t& lo) {
    __nv_bfloat16 ah = __float2bfloat16_rn(a), bh = __float2bfloat16_rn(b);
    float ar = a - __bfloat162float(ah), br = b - __bfloat162float(bh);
    __nv_bfloat16 al = __float2bfloat16_rn(ar), bl = __float2bfloat16_rn(br);
    hi = (uint32_t)__bfloat16_as_ushort(ah) | ((uint32_t)__bfloat16_as_ushort(bh) << 16);
    lo = (uint32_t)__bfloat16_as_ushort(al) | ((uint32_t)__bfloat16_as_ushort(bl) << 16);
}

// ---------------- scratch (device globals) ----------------
__device__ float  g_x   [(long long)Mr * GDc];          // emb @ W_proj [B,S,384]
__device__ float  g_hmid[(long long)Mr * 128];
__device__ float  g_hT  [(long long)4 * 2 * 128 * 8192];
__device__ float  g_vT  [(long long)4 * 128 * 8192];
__device__ float2 g_tw  [HALFN];

// ---------------- twiddles ----------------
__global__ void k_twiddle() {
    int k = blockIdx.x * 256 + threadIdx.x;
    double a = -2.0 * 3.14159265358979323846 * (double)k / (double)NFFT;
    g_tw[k] = make_float2((float)cos(a), (float)sin(a));
}

// ---------------- tensor-core GEMMs (bf16 3-term split) ----------------
// MODE 0: g_x = emb @ W_proj                       (NC=384)
// MODE 1: g_hmid = gelu(LN(rope(emb) @ W1 + b1))   (NC=128, rope fused in fetch)
// MODE 2: g_hT   = L1norm((g_hmid@W2+b2)*ffs), T   (NC=256)
// MODE 3: out    = v^T @ out_proj  (A col-major)   (NC=128)
#define STG 21504
#define AHo 0
#define ALo 6144
#define BHo 12288
#define BLo 16896

template<int MODE>
__global__ __launch_bounds__(256, 2)
void k_mma(const float* __restrict__ Aext, const float* __restrict__ W,
           const float* __restrict__ bias, const float* __restrict__ gain,
           const float* __restrict__ beta, float* __restrict__ Cext,
           const int* __restrict__ pos)
{
    constexpr int  NC   = (MODE == 0) ? 384 : (MODE == 2) ? 256 : 128;
    constexpr bool KMAJ = (MODE == 3);
    extern __shared__ char dsm[];

    const int tid = threadIdx.x;
    const int m0  = blockIdx.x * 128;
    const int n0  = blockIdx.y * 128;
    const int wid = tid >> 5, lid = tid & 31;
    const int wm  = wid >> 2, wn = wid & 3;

    const float* A;
    if      (MODE == 0) A = Aext;
    else if (MODE == 1) A = Aext;   // emb, rope applied in fetch
    else if (MODE == 2) A = g_hmid;
    else                A = g_vT + (size_t)(m0 >> 13) * (128 * 8192) + (m0 & 8191);

    float acc[4][4][4];
#pragma unroll
    for (int mi = 0; mi < 4; mi++)
#pragma unroll
        for (int ni = 0; ni < 4; ni++)
#pragma unroll
            for (int q = 0; q < 4; q++) acc[mi][ni][q] = 0.f;

    float4 ra0, ra1, rb0, rb1;
    const int arow = tid >> 1, akh = (tid & 1) * 8;
    const int krow = tid >> 4, nq8 = (tid & 15) * 8;

    auto fetch = [&](int kt) {
        if (KMAJ) {
            const float* ap = A + (size_t)(kt + krow) * 8192 + nq8;
            ra0 = *(const float4*)ap; ra1 = *(const float4*)(ap + 4);
        } else {
            const float* ap = A + (size_t)(m0 + arow) * 128 + kt + akh;
            ra0 = *(const float4*)ap; ra1 = *(const float4*)(ap + 4);
            if (MODE == 1) {
                float r[8];
                *(float4*)r = ra0; *(float4*)(r + 4) = ra1;
                float p = (float)pos[m0 + arow];
#pragma unroll
                for (int u = 0; u < 4; u++) {
                    int j = ((kt + akh) >> 1) + u;
                    float theta = exp2f(-(float)j * 0.20762050593046015f);
                    float sa, ca; sincosf(p * theta, &sa, &ca);
                    float xe = r[2 * u], xo = r[2 * u + 1];
                    r[2 * u]     = xe * ca - xo * sa;
                    r[2 * u + 1] = xe * sa + xo * ca;
                }
                ra0 = *(float4*)r; ra1 = *(float4*)(r + 4);
            }
        }
        const float* bp = W + (size_t)(kt + krow) * NC + n0 + nq8;
        rb0 = *(const float4*)bp; rb1 = *(const float4*)(bp + 4);
    };
    auto stage = [&](int s) {
        char* sb = dsm + s * STG;
        uint32_t h0, l0, h1, l1, h2, l2, h3, l3;
        split2(ra0.x, ra0.y, h0, l0); split2(ra0.z, ra0.w, h1, l1);
        split2(ra1.x, ra1.y, h2, l2); split2(ra1.z, ra1.w, h3, l3);
        if (KMAJ) {
            uint32_t* pH = (uint32_t*)(sb + AHo + krow * 272 + nq8 * 2);
            uint32_t* pL = (uint32_t*)(sb + ALo + krow * 272 + nq8 * 2);
            pH[0] = h0; pH[1] = h1; pH[2] = h2; pH[3] = h3;
            pL[0] = l0; pL[1] = l1; pL[2] = l2; pL[3] = l3;
        } else {
            uint32_t* pH = (uint32_t*)(sb + AHo + arow * 48 + akh * 2);
            uint32_t* pL = (uint32_t*)(sb + ALo + arow * 48 + akh * 2);
            pH[0] = h0; pH[1] = h1; pH[2] = h2; pH[3] = h3;
            pL[0] = l0; pL[1] = l1; pL[2] = l2; pL[3] = l3;
        }
        split2(rb0.x, rb0.y, h0, l0); split2(rb0.z, rb0.w, h1, l1);
        split2(rb1.x, rb1.y, h2, l2); split2(rb1.z, rb1.w, h3, l3);
        uint32_t* pH = (uint32_t*)(sb + BHo + krow * 272 + nq8 * 2);
        uint32_t* pL = (uint32_t*)(sb + BLo + krow * 272 + nq8 * 2);
        pH[0] = h0; pH[1] = h1; pH[2] = h2; pH[3] = h3;
        pL[0] = l0; pL[1] = l1; pL[2] = l2; pL[3] = l3;
    };

    auto compute = [&](int s) {
        char* sb = dsm + s * STG;
        uint32_t Ah[4][4], Al[4][4];
        if (!KMAJ) {
            int ar = wm * 64 + (lid & 15);
            int ac = ((lid >> 4) & 1) * 16;
#pragma unroll
            for (int mi = 0; mi < 4; mi++) {
                ldm4(Ah[mi], sb + AHo + (ar + mi * 16) * 48 + ac);
                ldm4(Al[mi], sb + ALo + (ar + mi * 16) * 48 + ac);
            }
        } else {
            int kr = ((lid >> 4) & 1) * 8 + (lid & 7);
            int mc = wm * 64 + ((lid >> 3) & 1) * 8;
#pragma unroll
            for (int mi = 0; mi < 4; mi++) {
                ldm4t(Ah[mi], sb + AHo + kr * 272 + (mc + mi * 16) * 2);
                ldm4t(Al[mi], sb + ALo + kr * 272 + (mc + mi * 16) * 2);
            }
        }
        int kr = ((lid >> 3) & 1) * 8 + (lid & 7);
        int ncb = wn * 32 + ((lid >> 4) & 1) * 8;
#pragma unroll
        for (int p = 0; p < 2; p++) {
            uint32_t Bh[4], Bl[4];
            ldm4t(Bh, sb + BHo + kr * 272 + (ncb + p * 16) * 2);
            ldm4t(Bl, sb + BLo + kr * 272 + (ncb + p * 16) * 2);
#pragma unroll
            for (int q = 0; q < 2; q++) {
                int ni = p * 2 + q;
#pragma unroll
                for (int mi = 0; mi < 4; mi++) {
                    mmabf(acc[mi][ni], Ah[mi], Bh + 2 * q);
                    mmabf(acc[mi][ni], Ah[mi], Bl + 2 * q);
                    mmabf(acc[mi][ni], Al[mi], Bh + 2 * q);
                }
            }
        }
    };

    fetch(0); stage(0);
    __syncthreads();
#pragma unroll 1
    for (int c = 0; c < 8; c++) {
        if (c < 7) fetch((c + 1) * 16);
        compute(c & 1);
        if (c < 7) stage((c + 1) & 1);
        __syncthreads();
    }

    // ---------------- epilogues ----------------
    if (MODE == 0 || MODE == 3) {
        float* C = (MODE == 0) ? g_x : Cext;
#pragma unroll
        for (int mi = 0; mi < 4; mi++)
#pragma unroll
            for (int ni = 0; ni < 4; ni++) {
                int r0 = m0 + wm * 64 + mi * 16 + (lid >> 2);
                int cc = n0 + wn * 32 + ni * 8 + 2 * (lid & 3);
                *(float2*)(C + (size_t)r0 * NC + cc)       = make_float2(acc[mi][ni][0], acc[mi][ni][1]);
                *(float2*)(C + (size_t)(r0 + 8) * NC + cc) = make_float2(acc[mi][ni][2], acc[mi][ni][3]);
            }
        return;
    }

    // MODES 1/2: dump fragments to smem [128][129]
    float* Ep = (float*)dsm;
    __syncthreads();
#pragma unroll
    for (int mi = 0; mi < 4; mi++)
#pragma unroll
        for (int ni = 0; ni < 4; ni++) {
            int r0 = wm * 64 + mi * 16 + (lid >> 2);
            int cc = wn * 32 + ni * 8 + 2 * (lid & 3);
            Ep[r0 * 129 + cc]           = acc[mi][ni][0];
            Ep[r0 * 129 + cc + 1]       = acc[mi][ni][1];
            Ep[(r0 + 8) * 129 + cc]     = acc[mi][ni][2];
            Ep[(r0 + 8) * 129 + cc + 1] = acc[mi][ni][3];
        }
    __syncthreads();

    int row = tid >> 1, half = tid & 1;
    float* rp = Ep + row * 129 + half * 64;

    if (MODE == 1) {
        float s = 0.f, s2 = 0.f;
#pragma unroll 4
        for (int i = 0; i < 64; i++) {
            float x = rp[i] + bias[half * 64 + i];
            s += x; s2 += x * x;
        }
        s  += __shfl_xor_sync(0xffffffffu, s,  1);
        s2 += __shfl_xor_sync(0xffffffffu, s2, 1);
        float mu  = s * (1.f / 128.f);
        float var = s2 * (1.f / 128.f) - mu * mu;
        float rs  = rsqrtf(var + 1e-5f);
        float* op = g_hmid + (size_t)(m0 + row) * 128 + half * 64;
#pragma unroll 1
        for (int i = 0; i < 16; i++) {
            float4 o;
            float* po = (float*)&o;
#pragma unroll
            for (int j = 0; j < 4; j++) {
                int cc = half * 64 + i * 4 + j;
                float x  = rp[i * 4 + j] + bias[cc];
                float xn = (x - mu) * rs * gain[cc] + beta[cc];
                po[j] = 0.5f * xn * (1.f + erff(xn * 0.70710678118654752f));
            }
            *(float4*)(op + i * 4) = o;
        }
    } else { // MODE 2
        float s = 0.f;
#pragma unroll 4
        for (int i = 0; i < 64; i++) {
            int gc = n0 + half * 64 + i;
            float x = (rp[i] + bias[gc]) * gain[gc];
            s += fabsf(x);
        }
        s += __shfl_xor_sync(0xffffffffu, s, 1);
        float rsc = 1.f / (s + 1e-8f);
#pragma unroll 4
        for (int i = 0; i < 64; i++) {
            int gc = n0 + half * 64 + i;
            rp[i] = (rp[i] + bias[gc]) * gain[gc] * rsc;
        }
        __syncthreads();
        float* dst = g_hT + (size_t)((m0 >> 13) * 2 + (n0 >> 7)) * (128 * 8192) + (m0 & 8191);
#pragma unroll 1
        for (int ccs = 0; ccs < 16; ccs++) {
            int cc = wid * 16 + ccs;
            float* dp = dst + (size_t)cc * 8192;
#pragma unroll
            for (int sq = 0; sq < 4; sq++)
                dp[sq * 32 + lid] = Ep[(sq * 32 + lid) * 129 + cc];
        }
    }
}

// ---------------- FFT recurrence + fused depthwise conv ----------------
// z_list[g][b,d,s] = conv_flat[b, d*24576 + g*8192 + s]  (flat [S,384] buffer)
// conv_flat[f] = cb[c] + w1[c]*X[f] + w0[c]*X[f-384] + w2[c]*X[f+384], c = f%384
__global__ __launch_bounds__(1024, 1)
void k_fftrec(const float* __restrict__ Bp, const float* __restrict__ cw,
              const float* __restrict__ cb) {
    extern __shared__ float2 sh[];
    __shared__ float s_w[1152];
    __shared__ float s_b[384];
    int b = blockIdx.x >> 7, d = blockIdx.x & 127;
    int t = threadIdx.x;
    if (t < 384) s_b[t] = cb[t];
    if (t >= 512 && t < 512 + 384) {
        int i = t - 512;
        s_w[i] = cw[i]; s_w[i + 384] = cw[i + 384]; s_w[i + 768] = cw[i + 768];
    }
    __syncthreads();

    const float* X = g_x + (size_t)b * (8192 * 384);
    const int fbase = d * 24576;     // flat offset of this d's slice
    const int FMAX = 8192 * 384;

    auto ztap = [&](int j) -> float {       // j in [0, 24576)
        int f = fbase + j;
        int c = j % 384;
        float a = s_b[c] + s_w[3 * c + 1] * X[f];
        if (f >= 384)        a += s_w[3 * c]     * X[f - 384];
        if (f + 384 < FMAX)  a += s_w[3 * c + 2] * X[f + 384];
        return a;
    };

    float vv[8];
#pragma unroll
    for (int k = 0; k < 8; k++) vv[k] = ztap(16384 + t + k * 1024);

    for (int it = 0; it < 2; it++) {
        const float* h = g_hT + (size_t)((b * 2 + it) * 128 + d) * 8192;

        // F1: radix-16 (lg13+lg11), fused with pack+zero-pad
        {
            float2 x[16];
#pragma unroll
            for (int r = 0; r < 4; r++) {
                float2 x0 = make_float2(vv[r],     h[t + 1024 * r]);
                float2 x1 = make_float2(vv[r + 4], h[t + 1024 * r + 4096]);
                float2 W1 = g_tw[t + 1024 * r];
                float2 W2 = make_float2(W1.y, -W1.x);
                float2 W3 = cmul(W1, W1);
                float2 t02m = cmul(x0, W1);
                float2 t13m = cmul(x1, W2);
                x[r]      = cadd(x0, x1);
                x[r + 4]  = cmul(csub(x0, x1), W3);
                x[r + 8]  = cadd(t02m, t13m);
                x[r + 12] = cmul(csub(t02m, t13m), W3);
            }
            float2 Wl2 = g_tw[4 * t];
#pragma unroll
            for (int q = 0; q < 4; q++) fwd4(x[4 * q], x[4 * q + 1], x[4 * q + 2], x[4 * q + 3], Wl2);
#pragma unroll
            for (int r = 0; r < 16; r++) sh[PD(t + 1024 * r)] = x[r];
        }
        __syncthreads();

        // F2: radix-16 (lg9+lg7)
        {
            int blk = t >> 6, off = t & 63;
            int base = blk * 1024 + off;
            float2 x[16];
#pragma unroll
            for (int r = 0; r < 16; r++) x[r] = sh[PD(base + 64 * r)];
#pragma unroll
            for (int r = 0; r < 4; r++) fwd4(x[r], x[r + 4], x[r + 8], x[r + 12], g_tw[16 * off + 1024 * r]);
            float2 Wl2 = g_tw[64 * off];
#pragma unroll
            for (int q = 0; q < 4; q++) fwd4(x[4 * q], x[4 * q + 1], x[4 * q + 2], x[4 * q + 3], Wl2);
#pragma unroll
            for (int r = 0; r < 16; r++) sh[PD(base + 64 * r)] = x[r];
        }
        __syncthreads();

        // F3: radix-16 (lg5+lg3)
        {
            int blk = t >> 2, off = t & 3;
            int base = blk * 64 + off;
            float2 x[16];
#pragma unroll
            for (int r = 0; r < 16; r++) x[r] = sh[PD(base + 4 * r)];
#pragma unroll
            for (int r = 0; r < 4; r++) fwd4(x[r], x[r + 4], x[r + 8], x[r + 12], g_tw[256 * off + 1024 * r]);
            float2 Wl2 = g_tw[1024 * off];
#pragma unroll
            for (int q = 0; q < 4; q++) fwd4(x[4 * q], x[4 * q + 1], x[4 * q + 2], x[4 * q + 3], Wl2);
#pragma unroll
            for (int r = 0; r < 16; r++) sh[PD(base + 4 * r)] = x[r];
        }
        __syncthreads();

        // F4: radix-4 (lg1)
#pragma unroll
        for (int k = 0; k < 4; k++) {
            int q4 = (t + 1024 * k) * 4;
            float2 y0 = sh[PD(q4)], y1 = sh[PD(q4 + 1)], y2 = sh[PD(q4 + 2)], y3 = sh[PD(q4 + 3)];
            fwd4(y0, y1, y2, y3, make_float2(1.f, 0.f));
            sh[PD(q4)] = y0; sh[PD(q4 + 1)] = y1; sh[PD(q4 + 2)] = y2; sh[PD(q4 + 3)] = y3;
        }
        __syncthreads();

        // spectral multiply + I1 (lg0+lg2)
        {
            int e0 = t << 4;
            float2 x[16];
#pragma unroll
            for (int r = 0; r < 16; r++) x[r] = sh[PD(e0 + r)];
#pragma unroll
            for (int r = 0; r < 16; r++) {
                int p  = e0 + r;
                int kk = __brev(p) >> 18;
                int k2 = (16384 - kk) & 16383;
                int p2 = __brev(k2) >> 18;
                float2 Q = sh[PD(p2)];
                float2 P = x[r];
                float vx = 0.5f * (P.x + Q.x), vy = 0.5f * (P.y - Q.y);
                float hx = 0.5f * (P.y + Q.y), hy = 0.5f * (Q.x - P.x);
                x[r] = make_float2(vx * hx - vy * hy, vx * hy + vy * hx);
            }
#pragma unroll
            for (int q = 0; q < 4; q++) inv4(x[4 * q], x[4 * q + 1], x[4 * q + 2], x[4 * q + 3], make_float2(1.f, 0.f));
#pragma unroll
            for (int r = 0; r < 4; r++) inv4(x[r], x[r + 4], x[r + 8], x[r + 12], g_tw[1024 * r]);
            __syncthreads();
#pragma unroll
            for (int r = 0; r < 16; r++) sh[PD(e0 + r)] = x[r];
        }
        __syncthreads();

        // I2: radix-16 (lg4+lg6)
        {
            int blk = t >> 4, off = t & 15;
            int base = blk * 256 + off;
            float2 x[16];
#pragma unroll
            for (int r = 0; r < 16; r++) x[r] = sh[PD(base + 16 * r)];
            float2 wA = g_tw[256 * off];
#pragma unroll
            for (int q = 0; q < 4; q++) inv4(x[4 * q], x[4 * q + 1], x[4 * q + 2], x[4 * q + 3], wA);
#pragma unroll
            for (int r = 0; r < 4; r++) inv4(x[r], x[r + 4], x[r + 8], x[r + 12], g_tw[64 * off + 1024 * r]);
#pragma unroll
            for (int r = 0; r < 16; r++) sh[PD(base + 16 * r)] = x[r];
        }
        __syncthreads();

        // I3: radix-16 (lg8+lg10)
        {
            int blk = t >> 8, off = t & 255;
            int base = blk * 4096 + off;
            float2 x[16];
#pragma unroll
            for (int r = 0; r < 16; r++) x[r] = sh[PD(base + 256 * r)];
            float2 wA = g_tw[16 * off];
#pragma unroll
            for (int q = 0; q < 4; q++) inv4(x[4 * q], x[4 * q + 1], x[4 * q + 2], x[4 * q + 3], wA);
#pragma unroll
            for (int r = 0; r < 4; r++) inv4(x[r], x[r + 4], x[r + 8], x[r + 12], g_tw[4 * off + 1024 * r]);
#pragma unroll
            for (int r = 0; r < 16; r++) sh[PD(base + 256 * r)] = x[r];
        }
        __syncthreads();

        // I4: final radix-4 (lg12) fused with conv(z) + v-update
        {
            float Bn = Bp[it * 128 + d];
#pragma unroll
            for (int jj = 0; jj < 4; jj++) {
                int j = t + jj * 1024;
                float2 x0 = sh[PD(j)];
                float2 x1 = sh[PD(j + 4096)];
                float2 x2 = sh[PD(j + 8192)];
                float2 x3 = sh[PD(j + 12288)];
                float2 w   = g_tw[j];
                float2 cw2 = make_float2(w.x, -w.y);
                float2 cw1 = cmul(cw2, cw2);
                float2 cw3 = make_float2(-cw2.y, cw2.x);
                float2 b1 = cmul(x1, cw1);
                float2 b3 = cmul(x3, cw1);
                float2 u0 = cadd(x0, b1), u1 = csub(x0, b1);
                float2 u2 = cadd(x2, b3), u3 = csub(x2, b3);
                float y0x = u0.x + (u2.x * cw2.x - u2.y * cw2.y);
                float y1x = u1.x + (u3.x * cw3.x - u3.y * cw3.y);
                float z0 = ztap(it * 8192 + j);
                float z1 = ztap(it * 8192 + j + 4096);
                vv[jj]     = z0 * (y0x * SCALE_U + Bn * vv[jj]);
                vv[jj + 4] = z1 * (y1x * SCALE_U + Bn * vv[jj + 4]);
            }
        }
        __syncthreads();
    }
    float* vo = g_vT + (size_t)(b * 128 + d) * 8192;
#pragma unroll
    for (int k = 0; k < 8; k++) vo[t + k * 1024] = vv[k];
}

extern "C" void kernel_launch(void* const* d_in, const int* in_sizes, int n_in,
                              void* d_out, int out_size) {
    const float* emb = (const float*)d_in[0];
    const float* Wp  = (const float*)d_in[1];
    const float* cw  = (const float*)d_in[2];
    const float* cb  = (const float*)d_in[3];
    const float* W1  = (const float*)d_in[4];
    const float* b1  = (const float*)d_in[5];
    const float* lng = (const float*)d_in[6];
    const float* lnb = (const float*)d_in[7];
    const float* W2  = (const float*)d_in[8];
    const float* b2  = (const float*)d_in[9];
    const float* ffs = (const float*)d_in[10];
    const float* op  = (const float*)d_in[11];
    const float* Bp  = (const float*)d_in[12];
    const int*   pos = (const int*)d_in[13];
    float* out = (float*)d_out;

    const int FFT_SMEM = 139776;
    const int MMA_SMEM_SMALL = 2 * STG;        // 43008 (modes 0,3)
    const int MMA_SMEM_BIG   = 128 * 129 * 4;  // 66048 (modes 1,2)
    cudaFuncSetAttribute(k_fftrec, cudaFuncAttributeMaxDynamicSharedMemorySize, FFT_SMEM);
    cudaFuncSetAttribute(k_mma<0>, cudaFuncAttributeMaxDynamicSharedMemorySize, MMA_SMEM_SMALL);
    cudaFuncSetAttribute(k_mma<1>, cudaFuncAttributeMaxDynamicSharedMemorySize, MMA_SMEM_BIG);
    cudaFuncSetAttribute(k_mma<2>, cudaFuncAttributeMaxDynamicSharedMemorySize, MMA_SMEM_BIG);
    cudaFuncSetAttribute(k_mma<3>, cudaFuncAttributeMaxDynamicSharedMemorySize, MMA_SMEM_SMALL);

    k_twiddle<<<32, 256>>>();
    k_mma<0><<<dim3(256, 3), 256, MMA_SMEM_SMALL>>>(emb, Wp, nullptr, nullptr, nullptr, nullptr, nullptr);
    k_mma<1><<<dim3(256, 1), 256, MMA_SMEM_BIG>>>(emb, W1, b1, lng, lnb, nullptr, pos);
    k_mma<2><<<dim3(256, 2), 256, MMA_SMEM_BIG>>>(nullptr, W2, b2, ffs, nullptr, nullptr, nullptr);
    k_fftrec<<<512, 1024, FFT_SMEM>>>(Bp, cw, cb);
    k_mma<3><<<dim3(256, 1), 256, MMA_SMEM_SMALL>>>(nullptr, op, nullptr, nullptr, nullptr, out, nullptr);
}